// round 2
// baseline (speedup 1.0000x reference)
#include <cuda_runtime.h>

#define AA 128      // image height == width
#define NN 64       // glimpse size
#define HD 512
#define NBATCH 2048
#define XSTR 132    // padded x row stride in smem (floats)

// Filterbanks, stored transposed for broadcast-friendly smem access later.
// g_FXT[c*64 + m] = F_X[m][c] / sum(F_X)
// g_FYT[a*64 + n] = gamma * F_Y[n][a] / sum(F_Y)
__device__ float g_FXT[AA * NN];
__device__ float g_FYT[AA * NN];

// ---------------------------------------------------------------------------
// Kernel 0: compute params from h[0], build filterbanks (global-sum norm),
// fold gamma into F_Y. One block, 256 threads.
// ---------------------------------------------------------------------------
__global__ void fb_setup(const float* __restrict__ h,
                         const float* __restrict__ Ww,
                         const float* __restrict__ Wb) {
    __shared__ float p[5];
    __shared__ float redx[256];
    __shared__ float redy[256];
    __shared__ float scales[2];
    const int tid  = threadIdx.x;
    const int wid  = tid >> 5;
    const int lane = tid & 31;

    // params[j] = h[0] . Ww[j] + Wb[j]   (5 warps, one per param)
    if (wid < 5) {
        float s = 0.f;
        for (int k = lane; k < HD; k += 32) s += h[k] * Ww[wid * HD + k];
        #pragma unroll
        for (int o = 16; o; o >>= 1) s += __shfl_down_sync(0xffffffffu, s, o);
        if (lane == 0) p[wid] = s + Wb[wid];
    }
    __syncthreads();

    const float gtX   = p[0];
    const float gtY   = p[1];
    const float var   = expf(p[2] + 1e-8f);
    const float d     = expf(p[3]) * (float)(AA - 1) / (float)(NN - 1);
    const float gamma = expf(p[4]);
    const float gX    = (float)(AA + 1) * (gtX + 1.f) * 0.5f;
    const float gY    = (float)(AA + 1) * (gtY + 1.f) * 0.5f;
    const float inv2v = 0.5f / var;

    float sx = 0.f, sy = 0.f;
    for (int idx = tid; idx < AA * NN; idx += 256) {
        const int n = idx >> 7;          // 0..63
        const int a = idx & (AA - 1);    // 0..127
        const float off = ((float)n - 32.5f) * d;  // (i - N/2 - 0.5)*d
        const float dx = (float)a - (gX + off);
        const float dy = (float)a - (gY + off);
        const float fx = expf(-dx * dx * inv2v);
        const float fy = expf(-dy * dy * inv2v);
        g_FXT[a * NN + n] = fx;
        g_FYT[a * NN + n] = fy;
        sx += fx;
        sy += fy;
    }
    redx[tid] = sx;
    redy[tid] = sy;
    __syncthreads();
    for (int s = 128; s; s >>= 1) {
        if (tid < s) { redx[tid] += redx[tid + s]; redy[tid] += redy[tid + s]; }
        __syncthreads();
    }
    if (tid == 0) { scales[0] = 1.f / redx[0]; scales[1] = gamma / redy[0]; }
    __syncthreads();
    const float isx = scales[0];
    const float gsy = scales[1];
    for (int idx = tid; idx < AA * NN; idx += 256) {
        g_FXT[idx] *= isx;
        g_FYT[idx] *= gsy;
    }
}

// ---------------------------------------------------------------------------
// Main kernel: one block per (batch, which). Two smem GEMMs:
//   W[a][m]   = sum_c x[a][c]   * FXT[c][m]      (128x64 = 1.05 MFMA)
//   out[n][m] = sum_a FYT[a][n] * W[a][m]        (64x64  = 0.52 MFMA)
// ---------------------------------------------------------------------------
__global__ __launch_bounds__(256, 1)
void fb_main(const float* __restrict__ x,
             const float* __restrict__ xh,
             float* __restrict__ out) {
    extern __shared__ float smem[];
    float* xs  = smem;                   // [128][132]
    float* fxt = smem + AA * XSTR;       // [c][64]
    float* fyt = fxt + AA * NN;          // [a][64]
    float* ws  = fyt + AA * NN;          // [a][64]

    const int tid   = threadIdx.x;
    const int b     = blockIdx.x;
    const int which = blockIdx.y;
    const float* __restrict__ xin =
        (which ? xh : x) + (size_t)b * (AA * AA);

    // ---- load x tile (coalesced float4) + filterbanks into smem ----
    const float4* x4 = (const float4*)xin;
    #pragma unroll
    for (int i = tid; i < AA * AA / 4; i += 256) {
        const int a  = i >> 5;           // row
        const int c4 = i & 31;           // float4 within row
        *(float4*)&xs[a * XSTR + c4 * 4] = x4[i];
    }
    const float4* gfx4 = (const float4*)g_FXT;
    const float4* gfy4 = (const float4*)g_FYT;
    #pragma unroll
    for (int i = tid; i < AA * NN / 4; i += 256) {
        *(float4*)&fxt[i * 4] = gfx4[i];
        *(float4*)&fyt[i * 4] = gfy4[i];
    }
    __syncthreads();

    // ---- stage 1: W = x @ F_X^T, per-thread 4a x 8m tile ----
    {
        const int am = tid >> 3;   // 0..31
        const int mg = tid & 7;    // 0..7
        const int a0 = am * 4;
        const int m0 = mg * 8;
        float acc[4][8];
        #pragma unroll
        for (int i = 0; i < 4; i++)
            #pragma unroll
            for (int j = 0; j < 8; j++) acc[i][j] = 0.f;

        #pragma unroll 4
        for (int c = 0; c < AA; c++) {
            const float4 f0 = *(const float4*)&fxt[c * NN + m0];
            const float4 f1 = *(const float4*)&fxt[c * NN + m0 + 4];
            const float fv[8] = {f0.x, f0.y, f0.z, f0.w, f1.x, f1.y, f1.z, f1.w};
            #pragma unroll
            for (int i = 0; i < 4; i++) {
                const float xv = xs[(a0 + i) * XSTR + c];
                #pragma unroll
                for (int j = 0; j < 8; j++)
                    acc[i][j] = fmaf(xv, fv[j], acc[i][j]);
            }
        }
        #pragma unroll
        for (int i = 0; i < 4; i++) {
            *(float4*)&ws[(a0 + i) * NN + m0] =
                make_float4(acc[i][0], acc[i][1], acc[i][2], acc[i][3]);
            *(float4*)&ws[(a0 + i) * NN + m0 + 4] =
                make_float4(acc[i][4], acc[i][5], acc[i][6], acc[i][7]);
        }
    }
    __syncthreads();

    // ---- stage 2: out = F_Y @ W, per-thread 4n x 4m tile ----
    {
        const int ng = tid >> 4;   // 0..15
        const int mg = tid & 15;   // 0..15
        const int n0 = ng * 4;
        const int m0 = mg * 4;
        float acc[4][4];
        #pragma unroll
        for (int i = 0; i < 4; i++)
            #pragma unroll
            for (int j = 0; j < 4; j++) acc[i][j] = 0.f;

        #pragma unroll 4
        for (int a = 0; a < AA; a++) {
            const float4 fy = *(const float4*)&fyt[a * NN + n0];
            const float4 wv = *(const float4*)&ws[a * NN + m0];
            const float fyv[4] = {fy.x, fy.y, fy.z, fy.w};
            const float wvv[4] = {wv.x, wv.y, wv.z, wv.w};
            #pragma unroll
            for (int i = 0; i < 4; i++)
                #pragma unroll
                for (int j = 0; j < 4; j++)
                    acc[i][j] = fmaf(fyv[i], wvv[j], acc[i][j]);
        }
        float* __restrict__ o =
            out + (size_t)b * (2 * NN * NN) + (size_t)which * (NN * NN);
        #pragma unroll
        for (int i = 0; i < 4; i++)
            *(float4*)&o[(n0 + i) * NN + m0] =
                make_float4(acc[i][0], acc[i][1], acc[i][2], acc[i][3]);
    }
}

// ---------------------------------------------------------------------------
static const int SMEM_BYTES = (AA * XSTR + 3 * AA * NN) * (int)sizeof(float);

extern "C" void kernel_launch(void* const* d_in, const int* in_sizes, int n_in,
                              void* d_out, int out_size) {
    const float* x  = (const float*)d_in[0];
    const float* xh = (const float*)d_in[1];
    const float* h  = (const float*)d_in[2];
    const float* Ww = (const float*)d_in[3];
    const float* Wb = (const float*)d_in[4];
    float* out = (float*)d_out;

    cudaFuncSetAttribute(fb_main, cudaFuncAttributeMaxDynamicSharedMemorySize,
                         SMEM_BYTES);

    fb_setup<<<1, 256>>>(h, Ww, Wb);
    fb_main<<<dim3(NBATCH, 2), 256, SMEM_BYTES>>>(x, xh, out);
}

// round 6
// speedup vs baseline: 1.6751x; 1.6751x over previous
#include <cuda_runtime.h>
#include <cuda_bf16.h>
#include <cstdint>

#define AA 128
#define NN 64
#define HD 512
#define NBATCH 2048
#define SPAD 136   // padded row stride in bf16 elems (68 words -> conflict-free frags)

// ---------------------------------------------------------------------------
// Filterbanks, bf16 hi/lo split, row-major [m][c] (64 x 128).
// g_fy has gamma folded in.
// ---------------------------------------------------------------------------
__device__ __nv_bfloat16 g_fxhi[NN * AA];
__device__ __nv_bfloat16 g_fxlo[NN * AA];
__device__ __nv_bfloat16 g_fyhi[NN * AA];
__device__ __nv_bfloat16 g_fylo[NN * AA];

// ---------------------------------------------------------------------------
// Setup: params from h[0], build normalized filterbanks, split hi/lo.
// ---------------------------------------------------------------------------
__global__ void fb_setup(const float* __restrict__ h,
                         const float* __restrict__ Ww,
                         const float* __restrict__ Wb) {
    __shared__ float p[5];
    __shared__ float redx[256], redy[256];
    __shared__ float scales[2];
    const int tid = threadIdx.x, wid = tid >> 5, lane = tid & 31;

    if (wid < 5) {
        float s = 0.f;
        for (int k = lane; k < HD; k += 32) s += h[k] * Ww[wid * HD + k];
        #pragma unroll
        for (int o = 16; o; o >>= 1) s += __shfl_down_sync(0xffffffffu, s, o);
        if (lane == 0) p[wid] = s + Wb[wid];
    }
    __syncthreads();

    const float var   = expf(p[2] + 1e-8f);
    const float d     = expf(p[3]) * (float)(AA - 1) / (float)(NN - 1);
    const float gamma = expf(p[4]);
    const float gX    = (float)(AA + 1) * (p[0] + 1.f) * 0.5f;
    const float gY    = (float)(AA + 1) * (p[1] + 1.f) * 0.5f;
    const float inv2v = 0.5f / var;

    float sx = 0.f, sy = 0.f;
    for (int idx = tid; idx < NN * AA; idx += 256) {
        const int m = idx >> 7, c = idx & 127;
        const float off = ((float)m - 32.5f) * d;
        const float dx = (float)c - (gX + off);
        const float dy = (float)c - (gY + off);
        sx += expf(-dx * dx * inv2v);
        sy += expf(-dy * dy * inv2v);
    }
    redx[tid] = sx; redy[tid] = sy;
    __syncthreads();
    for (int s = 128; s; s >>= 1) {
        if (tid < s) { redx[tid] += redx[tid + s]; redy[tid] += redy[tid + s]; }
        __syncthreads();
    }
    if (tid == 0) { scales[0] = 1.f / redx[0]; scales[1] = gamma / redy[0]; }
    __syncthreads();
    const float isx = scales[0], gsy = scales[1];

    for (int idx = tid; idx < NN * AA; idx += 256) {
        const int m = idx >> 7, c = idx & 127;
        const float off = ((float)m - 32.5f) * d;
        const float dx = (float)c - (gX + off);
        const float dy = (float)c - (gY + off);
        const float vx = expf(-dx * dx * inv2v) * isx;
        const float vy = expf(-dy * dy * inv2v) * gsy;
        __nv_bfloat16 hx = __float2bfloat16(vx);
        __nv_bfloat16 hy = __float2bfloat16(vy);
        g_fxhi[idx] = hx; g_fxlo[idx] = __float2bfloat16(vx - __bfloat162float(hx));
        g_fyhi[idx] = hy; g_fylo[idx] = __float2bfloat16(vy - __bfloat162float(hy));
    }
}

// ---------------------------------------------------------------------------
// mma.sync m16n8k16 bf16 (base PTX, compiles for compute_103)
// ---------------------------------------------------------------------------
__device__ __forceinline__ void mma16816(float* d, const uint32_t* a, const uint32_t* b) {
    asm volatile(
        "mma.sync.aligned.m16n8k16.row.col.f32.bf16.bf16.f32 "
        "{%0,%1,%2,%3}, {%4,%5,%6,%7}, {%8,%9}, {%0,%1,%2,%3};"
        : "+f"(d[0]), "+f"(d[1]), "+f"(d[2]), "+f"(d[3])
        : "r"(a[0]), "r"(a[1]), "r"(a[2]), "r"(a[3]), "r"(b[0]), "r"(b[1]));
}

__device__ __forceinline__ uint32_t pk2(__nv_bfloat16 a, __nv_bfloat16 b) {
    return (uint32_t)__bfloat16_as_ushort(a) | ((uint32_t)__bfloat16_as_ushort(b) << 16);
}

// smem byte offsets (all rows stride SPAD bf16 = 272 B)
#define OFF_XHI   0
#define OFF_XLO   34816
#define OFF_FXHI  69632
#define OFF_FXLO  87040
#define OFF_FYHI  104448
#define OFF_FYLO  121856
#define OFF_WHI   139264
#define OFF_WLO   156672
#define SMEM_MAIN 174080

__device__ __forceinline__ uint32_t ldpair(const unsigned char* smem, int byteoff,
                                           int row, int col) {
    return *(const uint32_t*)(smem + byteoff + (row * SPAD + col) * 2);
}

// ---------------------------------------------------------------------------
// Main: one image per block, 256 threads (8 warps).
// Stage1: D1[m][a] = sum_c FX[m][c] * X[a][c]   (M=64, N=128, K=128)
// Stage2: D2[n][m] = sum_a FY[n][a] * W[m][a]   (M=64, N=64,  K=128)
// 3-term bf16 split on both stages.
// ---------------------------------------------------------------------------
__global__ __launch_bounds__(256, 1)
void fb_main(const float* __restrict__ x,
             const float* __restrict__ xh,
             float* __restrict__ out) {
    extern __shared__ unsigned char smem[];
    const int tid  = threadIdx.x;
    const int w    = tid >> 5;
    const int lane = tid & 31;
    const int g    = lane >> 2;   // group row
    const int t    = lane & 3;    // thread-in-group
    const int b = blockIdx.x, which = blockIdx.y;
    const float* __restrict__ xin = (which ? xh : x) + (size_t)b * (AA * AA);

    // ---- convert X -> bf16 hi/lo into padded smem; copy filterbanks ----
    {
        const float4* x4 = (const float4*)xin;
        for (int i = tid; i < AA * AA / 4; i += 256) {
            const float4 v = x4[i];
            const int a  = i >> 5;
            const int c0 = (i & 31) * 4;
            __nv_bfloat16 h0 = __float2bfloat16(v.x), h1 = __float2bfloat16(v.y);
            __nv_bfloat16 h2 = __float2bfloat16(v.z), h3 = __float2bfloat16(v.w);
            __nv_bfloat16 l0 = __float2bfloat16(v.x - __bfloat162float(h0));
            __nv_bfloat16 l1 = __float2bfloat16(v.y - __bfloat162float(h1));
            __nv_bfloat16 l2 = __float2bfloat16(v.z - __bfloat162float(h2));
            __nv_bfloat16 l3 = __float2bfloat16(v.w - __bfloat162float(h3));
            const int boff = (a * SPAD + c0) * 2;
            *(uint2*)(smem + OFF_XHI + boff) = make_uint2(pk2(h0, h1), pk2(h2, h3));
            *(uint2*)(smem + OFF_XLO + boff) = make_uint2(pk2(l0, l1), pk2(l2, l3));
        }
        const uint32_t* fx_h = (const uint32_t*)g_fxhi;
        const uint32_t* fx_l = (const uint32_t*)g_fxlo;
        const uint32_t* fy_h = (const uint32_t*)g_fyhi;
        const uint32_t* fy_l = (const uint32_t*)g_fylo;
        for (int i = tid; i < NN * AA / 2; i += 256) {
            const int m = (2 * i) >> 7;
            const int c = (2 * i) & 127;
            const int boff = (m * SPAD + c) * 2;
            *(uint32_t*)(smem + OFF_FXHI + boff) = fx_h[i];
            *(uint32_t*)(smem + OFF_FXLO + boff) = fx_l[i];
            *(uint32_t*)(smem + OFF_FYHI + boff) = fy_h[i];
            *(uint32_t*)(smem + OFF_FYLO + boff) = fy_l[i];
        }
    }
    __syncthreads();

    // ---- stage 1: warps split (mw: 4 m-tiles of 16) x (nw: 2 a-halves of 64) ----
    {
        const int mw = w >> 1, nw = w & 1;
        const int m0 = mw * 16;
        const int abase = nw * 64;
        float acc[8][4];
        #pragma unroll
        for (int n = 0; n < 8; n++)
            #pragma unroll
            for (int j = 0; j < 4; j++) acc[n][j] = 0.f;

        #pragma unroll
        for (int k = 0; k < 8; k++) {
            const int c0 = k * 16;
            uint32_t ahh[4], all_[4];
            ahh[0] = ldpair(smem, OFF_FXHI, m0 + g,     c0 + 2 * t);
            ahh[1] = ldpair(smem, OFF_FXHI, m0 + g + 8, c0 + 2 * t);
            ahh[2] = ldpair(smem, OFF_FXHI, m0 + g,     c0 + 2 * t + 8);
            ahh[3] = ldpair(smem, OFF_FXHI, m0 + g + 8, c0 + 2 * t + 8);
            all_[0] = ldpair(smem, OFF_FXLO, m0 + g,     c0 + 2 * t);
            all_[1] = ldpair(smem, OFF_FXLO, m0 + g + 8, c0 + 2 * t);
            all_[2] = ldpair(smem, OFF_FXLO, m0 + g,     c0 + 2 * t + 8);
            all_[3] = ldpair(smem, OFF_FXLO, m0 + g + 8, c0 + 2 * t + 8);
            #pragma unroll
            for (int n = 0; n < 8; n++) {
                const int ar = abase + n * 8 + g;
                uint32_t bh[2], bl[2];
                bh[0] = ldpair(smem, OFF_XHI, ar, c0 + 2 * t);
                bh[1] = ldpair(smem, OFF_XHI, ar, c0 + 2 * t + 8);
                bl[0] = ldpair(smem, OFF_XLO, ar, c0 + 2 * t);
                bl[1] = ldpair(smem, OFF_XLO, ar, c0 + 2 * t + 8);
                mma16816(acc[n], ahh, bh);
                mma16816(acc[n], ahh, bl);
                mma16816(acc[n], all_, bh);
            }
        }
        // store W[m][a] hi/lo (packed pairs along a)
        #pragma unroll
        for (int n = 0; n < 8; n++) {
            const int ac = abase + n * 8 + 2 * t;
            const int r0 = m0 + g, r1 = m0 + g + 8;
            __nv_bfloat16 h0 = __float2bfloat16(acc[n][0]);
            __nv_bfloat16 h1 = __float2bfloat16(acc[n][1]);
            __nv_bfloat16 h2 = __float2bfloat16(acc[n][2]);
            __nv_bfloat16 h3 = __float2bfloat16(acc[n][3]);
            __nv_bfloat16 l0 = __float2bfloat16(acc[n][0] - __bfloat162float(h0));
            __nv_bfloat16 l1 = __float2bfloat16(acc[n][1] - __bfloat162float(h1));
            __nv_bfloat16 l2 = __float2bfloat16(acc[n][2] - __bfloat162float(h2));
            __nv_bfloat16 l3 = __float2bfloat16(acc[n][3] - __bfloat162float(h3));
            *(uint32_t*)(smem + OFF_WHI + (r0 * SPAD + ac) * 2) = pk2(h0, h1);
            *(uint32_t*)(smem + OFF_WLO + (r0 * SPAD + ac) * 2) = pk2(l0, l1);
            *(uint32_t*)(smem + OFF_WHI + (r1 * SPAD + ac) * 2) = pk2(h2, h3);
            *(uint32_t*)(smem + OFF_WLO + (r1 * SPAD + ac) * 2) = pk2(l2, l3);
        }
    }
    __syncthreads();

    // ---- stage 2: warps split (mw: 4 n-tiles of 16) x (nw: 2 m-halves of 32) ----
    {
        const int mw = w >> 1, nw = w & 1;
        const int n0 = mw * 16;
        const int mbase = nw * 32;
        float acc[4][4];
        #pragma unroll
        for (int n = 0; n < 4; n++)
            #pragma unroll
            for (int j = 0; j < 4; j++) acc[n][j] = 0.f;

        #pragma unroll
        for (int k = 0; k < 8; k++) {
            const int a0 = k * 16;
            uint32_t ahh[4], all_[4];
            ahh[0] = ldpair(smem, OFF_FYHI, n0 + g,     a0 + 2 * t);
            ahh[1] = ldpair(smem, OFF_FYHI, n0 + g + 8, a0 + 2 * t);
            ahh[2] = ldpair(smem, OFF_FYHI, n0 + g,     a0 + 2 * t + 8);
            ahh[3] = ldpair(smem, OFF_FYHI, n0 + g + 8, a0 + 2 * t + 8);
            all_[0] = ldpair(smem, OFF_FYLO, n0 + g,     a0 + 2 * t);
            all_[1] = ldpair(smem, OFF_FYLO, n0 + g + 8, a0 + 2 * t);
            all_[2] = ldpair(smem, OFF_FYLO, n0 + g,     a0 + 2 * t + 8);
            all_[3] = ldpair(smem, OFF_FYLO, n0 + g + 8, a0 + 2 * t + 8);
            #pragma unroll
            for (int mt = 0; mt < 4; mt++) {
                const int mr = mbase + mt * 8 + g;
                uint32_t bh[2], bl[2];
                bh[0] = ldpair(smem, OFF_WHI, mr, a0 + 2 * t);
                bh[1] = ldpair(smem, OFF_WHI, mr, a0 + 2 * t + 8);
                bl[0] = ldpair(smem, OFF_WLO, mr, a0 + 2 * t);
                bl[1] = ldpair(smem, OFF_WLO, mr, a0 + 2 * t + 8);
                mma16816(acc[mt], ahh, bh);
                mma16816(acc[mt], ahh, bl);
                mma16816(acc[mt], all_, bh);
            }
        }
        // write output: D2[n][m], rows n0+g / n0+g+8, cols mbase+mt*8+2t(+1)
        float* __restrict__ o = out + (size_t)b * (2 * NN * NN)
                                    + (size_t)which * (NN * NN);
        #pragma unroll
        for (int mt = 0; mt < 4; mt++) {
            const int mc = mbase + mt * 8 + 2 * t;
            *(float2*)(o + (n0 + g) * NN + mc)     = make_float2(acc[mt][0], acc[mt][1]);
            *(float2*)(o + (n0 + g + 8) * NN + mc) = make_float2(acc[mt][2], acc[mt][3]);
        }
    }
}

// ---------------------------------------------------------------------------
extern "C" void kernel_launch(void* const* d_in, const int* in_sizes, int n_in,
                              void* d_out, int out_size) {
    const float* x  = (const float*)d_in[0];
    const float* xh = (const float*)d_in[1];
    const float* h  = (const float*)d_in[2];
    const float* Ww = (const float*)d_in[3];
    const float* Wb = (const float*)d_in[4];
    float* out = (float*)d_out;

    cudaFuncSetAttribute(fb_main, cudaFuncAttributeMaxDynamicSharedMemorySize, SMEM_MAIN);

    fb_setup<<<1, 256>>>(h, Ww, Wb);
    fb_main<<<dim3(NBATCH, 2), 256, SMEM_MAIN>>>(x, xh, out);
}

// round 7
// speedup vs baseline: 2.9142x; 1.7397x over previous
#include <cuda_runtime.h>
#include <cuda_bf16.h>
#include <cstdint>

#define AA 128
#define NN 64
#define HD 512
#define NBATCH 2048
#define SPAD 136   // padded row stride in bf16 elems (68 words -> conflict-free frags)

// ---------------------------------------------------------------------------
// Filterbanks in MMA A-fragment order, bf16 hi/lo packed pairs.
// Index: ((mw*32 + lane)*8 + k)*4 + r   (uint32 each = 2 bf16)
//   row = mw*16 + g + (r&1)*8,  col = k*16 + 2t + (r>>1)*8   (g=lane>>2, t=lane&3)
// g_fy has gamma folded in.
// ---------------------------------------------------------------------------
__device__ uint32_t g_fxhi_f[4096];
__device__ uint32_t g_fxlo_f[4096];
__device__ uint32_t g_fyhi_f[4096];
__device__ uint32_t g_fylo_f[4096];

__device__ __forceinline__ uint32_t pk2(__nv_bfloat16 a, __nv_bfloat16 b) {
    return (uint32_t)__bfloat16_as_ushort(a) | ((uint32_t)__bfloat16_as_ushort(b) << 16);
}

// ---------------------------------------------------------------------------
// Setup: params from h[0], normalization sums, then emit fragment-ordered
// hi/lo filterbank arrays.
// ---------------------------------------------------------------------------
__global__ void fb_setup(const float* __restrict__ h,
                         const float* __restrict__ Ww,
                         const float* __restrict__ Wb) {
    __shared__ float p[5];
    __shared__ float redx[256], redy[256];
    __shared__ float scales[2];
    const int tid = threadIdx.x, wid = tid >> 5, lane = tid & 31;

    if (wid < 5) {
        float s = 0.f;
        for (int k = lane; k < HD; k += 32) s += h[k] * Ww[wid * HD + k];
        #pragma unroll
        for (int o = 16; o; o >>= 1) s += __shfl_down_sync(0xffffffffu, s, o);
        if (lane == 0) p[wid] = s + Wb[wid];
    }
    __syncthreads();

    const float var   = expf(p[2] + 1e-8f);
    const float d     = expf(p[3]) * (float)(AA - 1) / (float)(NN - 1);
    const float gamma = expf(p[4]);
    const float gX    = (float)(AA + 1) * (p[0] + 1.f) * 0.5f;
    const float gY    = (float)(AA + 1) * (p[1] + 1.f) * 0.5f;
    const float inv2v = 0.5f / var;

    float sx = 0.f, sy = 0.f;
    for (int idx = tid; idx < NN * AA; idx += 256) {
        const int m = idx >> 7, c = idx & 127;
        const float off = ((float)m - 32.5f) * d;
        const float dx = (float)c - (gX + off);
        const float dy = (float)c - (gY + off);
        sx += expf(-dx * dx * inv2v);
        sy += expf(-dy * dy * inv2v);
    }
    redx[tid] = sx; redy[tid] = sy;
    __syncthreads();
    for (int s = 128; s; s >>= 1) {
        if (tid < s) { redx[tid] += redx[tid + s]; redy[tid] += redy[tid + s]; }
        __syncthreads();
    }
    if (tid == 0) { scales[0] = 1.f / redx[0]; scales[1] = gamma / redy[0]; }
    __syncthreads();
    const float isx = scales[0], gsy = scales[1];

    // Emit fragment-ordered arrays: 4096 uint32 per array.
    for (int i = tid; i < 4096; i += 256) {
        const int r    = i & 3;
        const int k    = (i >> 2) & 7;
        const int lne  = (i >> 5) & 31;
        const int mw   = i >> 10;
        const int g    = lne >> 2, t = lne & 3;
        const int row  = mw * 16 + g + (r & 1) * 8;        // filterbank row (0..63)
        const int col  = k * 16 + 2 * t + (r >> 1) * 8;    // image dim (0..127)
        const float off = ((float)row - 32.5f) * d;

        // FX value at (row, col) and (row, col+1)
        float dx0 = (float)col - (gX + off), dx1 = (float)(col + 1) - (gX + off);
        float vx0 = expf(-dx0 * dx0 * inv2v) * isx;
        float vx1 = expf(-dx1 * dx1 * inv2v) * isx;
        __nv_bfloat16 hx0 = __float2bfloat16(vx0), hx1 = __float2bfloat16(vx1);
        g_fxhi_f[i] = pk2(hx0, hx1);
        g_fxlo_f[i] = pk2(__float2bfloat16(vx0 - __bfloat162float(hx0)),
                          __float2bfloat16(vx1 - __bfloat162float(hx1)));

        float dy0 = (float)col - (gY + off), dy1 = (float)(col + 1) - (gY + off);
        float vy0 = expf(-dy0 * dy0 * inv2v) * gsy;
        float vy1 = expf(-dy1 * dy1 * inv2v) * gsy;
        __nv_bfloat16 hy0 = __float2bfloat16(vy0), hy1 = __float2bfloat16(vy1);
        g_fyhi_f[i] = pk2(hy0, hy1);
        g_fylo_f[i] = pk2(__float2bfloat16(vy0 - __bfloat162float(hy0)),
                          __float2bfloat16(vy1 - __bfloat162float(hy1)));
    }
}

// ---------------------------------------------------------------------------
// mma.sync m16n8k16 bf16 (base PTX, compiles for compute_103)
// ---------------------------------------------------------------------------
__device__ __forceinline__ void mma16816(float* d, const uint32_t* a, const uint32_t* b) {
    asm volatile(
        "mma.sync.aligned.m16n8k16.row.col.f32.bf16.bf16.f32 "
        "{%0,%1,%2,%3}, {%4,%5,%6,%7}, {%8,%9}, {%0,%1,%2,%3};"
        : "+f"(d[0]), "+f"(d[1]), "+f"(d[2]), "+f"(d[3])
        : "r"(a[0]), "r"(a[1]), "r"(a[2]), "r"(a[3]), "r"(b[0]), "r"(b[1]));
}

// smem byte offsets (rows stride SPAD bf16 = 272 B)
#define OFF_XHI   0
#define OFF_XLO   34816
#define OFF_WHI   69632
#define OFF_WLO   87040
#define SMEM_MAIN 104448

__device__ __forceinline__ uint32_t ldpair(const unsigned char* smem, int byteoff,
                                           int row, int col) {
    return *(const uint32_t*)(smem + byteoff + (row * SPAD + col) * 2);
}

// ---------------------------------------------------------------------------
// Main: one image per block, 256 threads (8 warps), 2 blocks/SM.
// Stage1: D1[m][a] = sum_c FX[m][c] * X[a][c]   (M=64, N=128, K=128)
// Stage2: D2[n][m] = sum_a FY[n][a] * W[m][a]   (M=64, N=64,  K=128)
// 3-term bf16 split on both stages; filterbank A-frags preloaded from gmem.
// ---------------------------------------------------------------------------
__global__ __launch_bounds__(256, 2)
void fb_main(const float* __restrict__ x,
             const float* __restrict__ xh,
             float* __restrict__ out) {
    extern __shared__ unsigned char smem[];
    const int tid  = threadIdx.x;
    const int w    = tid >> 5;
    const int lane = tid & 31;
    const int g    = lane >> 2;
    const int t    = lane & 3;
    const int mw   = w >> 1, nw = w & 1;
    const int b = blockIdx.x, which = blockIdx.y;
    const float* __restrict__ xin = (which ? xh : x) + (size_t)b * (AA * AA);

    // ---- preload FX A-fragments (8x LDG.128 x2, latency hidden by X load) ----
    uint32_t fah[8][4], fal[8][4];
    {
        const uint4* fh4 = (const uint4*)g_fxhi_f + (mw * 32 + lane) * 8;
        const uint4* fl4 = (const uint4*)g_fxlo_f + (mw * 32 + lane) * 8;
        #pragma unroll
        for (int k = 0; k < 8; k++) {
            uint4 vh = fh4[k];
            fah[k][0] = vh.x; fah[k][1] = vh.y; fah[k][2] = vh.z; fah[k][3] = vh.w;
            uint4 vl = fl4[k];
            fal[k][0] = vl.x; fal[k][1] = vl.y; fal[k][2] = vl.z; fal[k][3] = vl.w;
        }
    }

    // ---- X: load fp32, split hi/lo, STS into padded smem ----
    {
        const float4* x4 = (const float4*)xin;
        #pragma unroll 4
        for (int i = tid; i < AA * AA / 4; i += 256) {
            const float4 v = x4[i];
            const int a  = i >> 5;
            const int c0 = (i & 31) * 4;
            __nv_bfloat16 h0 = __float2bfloat16(v.x), h1 = __float2bfloat16(v.y);
            __nv_bfloat16 h2 = __float2bfloat16(v.z), h3 = __float2bfloat16(v.w);
            __nv_bfloat16 l0 = __float2bfloat16(v.x - __bfloat162float(h0));
            __nv_bfloat16 l1 = __float2bfloat16(v.y - __bfloat162float(h1));
            __nv_bfloat16 l2 = __float2bfloat16(v.z - __bfloat162float(h2));
            __nv_bfloat16 l3 = __float2bfloat16(v.w - __bfloat162float(h3));
            const int boff = (a * SPAD + c0) * 2;
            *(uint2*)(smem + OFF_XHI + boff) = make_uint2(pk2(h0, h1), pk2(h2, h3));
            *(uint2*)(smem + OFF_XLO + boff) = make_uint2(pk2(l0, l1), pk2(l2, l3));
        }
    }
    __syncthreads();

    // ---- stage 1 ----
    {
        const int abase = nw * 64;
        float acc[8][4];
        #pragma unroll
        for (int n = 0; n < 8; n++)
            #pragma unroll
            for (int j = 0; j < 4; j++) acc[n][j] = 0.f;

        #pragma unroll
        for (int k = 0; k < 8; k++) {
            const int c0 = k * 16;
            #pragma unroll
            for (int n = 0; n < 8; n++) {
                const int ar = abase + n * 8 + g;
                uint32_t bh[2], bl[2];
                bh[0] = ldpair(smem, OFF_XHI, ar, c0 + 2 * t);
                bh[1] = ldpair(smem, OFF_XHI, ar, c0 + 2 * t + 8);
                bl[0] = ldpair(smem, OFF_XLO, ar, c0 + 2 * t);
                bl[1] = ldpair(smem, OFF_XLO, ar, c0 + 2 * t + 8);
                mma16816(acc[n], fah[k], bh);
                mma16816(acc[n], fah[k], bl);
                mma16816(acc[n], fal[k], bh);
            }
        }

        // preload FY A-fragments into the (now dead) fah/fal regs; latency
        // hides behind the W-store + barrier below.
        {
            const uint4* fh4 = (const uint4*)g_fyhi_f + (mw * 32 + lane) * 8;
            const uint4* fl4 = (const uint4*)g_fylo_f + (mw * 32 + lane) * 8;
            #pragma unroll
            for (int k = 0; k < 8; k++) {
                uint4 vh = fh4[k];
                fah[k][0] = vh.x; fah[k][1] = vh.y; fah[k][2] = vh.z; fah[k][3] = vh.w;
                uint4 vl = fl4[k];
                fal[k][0] = vl.x; fal[k][1] = vl.y; fal[k][2] = vl.z; fal[k][3] = vl.w;
            }
        }

        // store W[m][a] hi/lo
        #pragma unroll
        for (int n = 0; n < 8; n++) {
            const int ac = abase + n * 8 + 2 * t;
            const int r0 = mw * 16 + g, r1 = r0 + 8;
            __nv_bfloat16 h0 = __float2bfloat16(acc[n][0]);
            __nv_bfloat16 h1 = __float2bfloat16(acc[n][1]);
            __nv_bfloat16 h2 = __float2bfloat16(acc[n][2]);
            __nv_bfloat16 h3 = __float2bfloat16(acc[n][3]);
            __nv_bfloat16 l0 = __float2bfloat16(acc[n][0] - __bfloat162float(h0));
            __nv_bfloat16 l1 = __float2bfloat16(acc[n][1] - __bfloat162float(h1));
            __nv_bfloat16 l2 = __float2bfloat16(acc[n][2] - __bfloat162float(h2));
            __nv_bfloat16 l3 = __float2bfloat16(acc[n][3] - __bfloat162float(h3));
            *(uint32_t*)(smem + OFF_WHI + (r0 * SPAD + ac) * 2) = pk2(h0, h1);
            *(uint32_t*)(smem + OFF_WLO + (r0 * SPAD + ac) * 2) = pk2(l0, l1);
            *(uint32_t*)(smem + OFF_WHI + (r1 * SPAD + ac) * 2) = pk2(h2, h3);
            *(uint32_t*)(smem + OFF_WLO + (r1 * SPAD + ac) * 2) = pk2(l2, l3);
        }
    }
    __syncthreads();

    // ---- stage 2 ----
    {
        const int mbase = nw * 32;
        float acc[4][4];
        #pragma unroll
        for (int n = 0; n < 4; n++)
            #pragma unroll
            for (int j = 0; j < 4; j++) acc[n][j] = 0.f;

        #pragma unroll
        for (int k = 0; k < 8; k++) {
            const int a0 = k * 16;
            #pragma unroll
            for (int mt = 0; mt < 4; mt++) {
                const int mr = mbase + mt * 8 + g;
                uint32_t bh[2], bl[2];
                bh[0] = ldpair(smem, OFF_WHI, mr, a0 + 2 * t);
                bh[1] = ldpair(smem, OFF_WHI, mr, a0 + 2 * t + 8);
                bl[0] = ldpair(smem, OFF_WLO, mr, a0 + 2 * t);
                bl[1] = ldpair(smem, OFF_WLO, mr, a0 + 2 * t + 8);
                mma16816(acc[mt], fah[k], bh);
                mma16816(acc[mt], fah[k], bl);
                mma16816(acc[mt], fal[k], bh);
            }
        }

        float* __restrict__ o = out + (size_t)b * (2 * NN * NN)
                                    + (size_t)which * (NN * NN);
        const int n0 = mw * 16;
        #pragma unroll
        for (int mt = 0; mt < 4; mt++) {
            const int mc = mbase + mt * 8 + 2 * t;
            *(float2*)(o + (n0 + g) * NN + mc)     = make_float2(acc[mt][0], acc[mt][1]);
            *(float2*)(o + (n0 + g + 8) * NN + mc) = make_float2(acc[mt][2], acc[mt][3]);
        }
    }
}

// ---------------------------------------------------------------------------
extern "C" void kernel_launch(void* const* d_in, const int* in_sizes, int n_in,
                              void* d_out, int out_size) {
    const float* x  = (const float*)d_in[0];
    const float* xh = (const float*)d_in[1];
    const float* h  = (const float*)d_in[2];
    const float* Ww = (const float*)d_in[3];
    const float* Wb = (const float*)d_in[4];
    float* out = (float*)d_out;

    cudaFuncSetAttribute(fb_main, cudaFuncAttributeMaxDynamicSharedMemorySize, SMEM_MAIN);

    fb_setup<<<1, 256>>>(h, Ww, Wb);
    fb_main<<<dim3(NBATCH, 2), 256, SMEM_MAIN>>>(x, xh, out);
}

// round 8
// speedup vs baseline: 3.0923x; 1.0611x over previous
#include <cuda_runtime.h>
#include <cuda_bf16.h>
#include <cstdint>

#define AA 128
#define NN 64
#define HD 512
#define NBATCH 2048
#define SPAD 136   // padded row stride in bf16 (68 words == 4 mod 32 -> ldmatrix conflict-free)

// ---------------------------------------------------------------------------
// Filterbanks in MMA A-fragment order, bf16 hi/lo packed pairs.
// Index: ((mw*32 + lane)*8 + k)*4 + r
//   row = mw*16 + g + (r&1)*8,  col = k*16 + 2t + (r>>1)*8
// g_fy has gamma folded in.
// ---------------------------------------------------------------------------
__device__ uint32_t g_fxhi_f[4096];
__device__ uint32_t g_fxlo_f[4096];
__device__ uint32_t g_fyhi_f[4096];
__device__ uint32_t g_fylo_f[4096];

__device__ __forceinline__ uint32_t pk2(__nv_bfloat16 a, __nv_bfloat16 b) {
    return (uint32_t)__bfloat16_as_ushort(a) | ((uint32_t)__bfloat16_as_ushort(b) << 16);
}

// ---------------------------------------------------------------------------
// Setup kernel (unchanged from R7)
// ---------------------------------------------------------------------------
__global__ void fb_setup(const float* __restrict__ h,
                         const float* __restrict__ Ww,
                         const float* __restrict__ Wb) {
    __shared__ float p[5];
    __shared__ float redx[256], redy[256];
    __shared__ float scales[2];
    const int tid = threadIdx.x, wid = tid >> 5, lane = tid & 31;

    if (wid < 5) {
        float s = 0.f;
        for (int k = lane; k < HD; k += 32) s += h[k] * Ww[wid * HD + k];
        #pragma unroll
        for (int o = 16; o; o >>= 1) s += __shfl_down_sync(0xffffffffu, s, o);
        if (lane == 0) p[wid] = s + Wb[wid];
    }
    __syncthreads();

    const float var   = expf(p[2] + 1e-8f);
    const float d     = expf(p[3]) * (float)(AA - 1) / (float)(NN - 1);
    const float gamma = expf(p[4]);
    const float gX    = (float)(AA + 1) * (p[0] + 1.f) * 0.5f;
    const float gY    = (float)(AA + 1) * (p[1] + 1.f) * 0.5f;
    const float inv2v = 0.5f / var;

    float sx = 0.f, sy = 0.f;
    for (int idx = tid; idx < NN * AA; idx += 256) {
        const int m = idx >> 7, c = idx & 127;
        const float off = ((float)m - 32.5f) * d;
        const float dx = (float)c - (gX + off);
        const float dy = (float)c - (gY + off);
        sx += expf(-dx * dx * inv2v);
        sy += expf(-dy * dy * inv2v);
    }
    redx[tid] = sx; redy[tid] = sy;
    __syncthreads();
    for (int s = 128; s; s >>= 1) {
        if (tid < s) { redx[tid] += redx[tid + s]; redy[tid] += redy[tid + s]; }
        __syncthreads();
    }
    if (tid == 0) { scales[0] = 1.f / redx[0]; scales[1] = gamma / redy[0]; }
    __syncthreads();
    const float isx = scales[0], gsy = scales[1];

    for (int i = tid; i < 4096; i += 256) {
        const int r    = i & 3;
        const int k    = (i >> 2) & 7;
        const int lne  = (i >> 5) & 31;
        const int mw   = i >> 10;
        const int g    = lne >> 2, t = lne & 3;
        const int row  = mw * 16 + g + (r & 1) * 8;
        const int col  = k * 16 + 2 * t + (r >> 1) * 8;
        const float off = ((float)row - 32.5f) * d;

        float dx0 = (float)col - (gX + off), dx1 = (float)(col + 1) - (gX + off);
        float vx0 = expf(-dx0 * dx0 * inv2v) * isx;
        float vx1 = expf(-dx1 * dx1 * inv2v) * isx;
        __nv_bfloat16 hx0 = __float2bfloat16(vx0), hx1 = __float2bfloat16(vx1);
        g_fxhi_f[i] = pk2(hx0, hx1);
        g_fxlo_f[i] = pk2(__float2bfloat16(vx0 - __bfloat162float(hx0)),
                          __float2bfloat16(vx1 - __bfloat162float(hx1)));

        float dy0 = (float)col - (gY + off), dy1 = (float)(col + 1) - (gY + off);
        float vy0 = expf(-dy0 * dy0 * inv2v) * gsy;
        float vy1 = expf(-dy1 * dy1 * inv2v) * gsy;
        __nv_bfloat16 hy0 = __float2bfloat16(vy0), hy1 = __float2bfloat16(vy1);
        g_fyhi_f[i] = pk2(hy0, hy1);
        g_fylo_f[i] = pk2(__float2bfloat16(vy0 - __bfloat162float(hy0)),
                          __float2bfloat16(vy1 - __bfloat162float(hy1)));
    }
}

// ---------------------------------------------------------------------------
// MMA + ldmatrix (both base PTX, compile for compute_103)
// ---------------------------------------------------------------------------
__device__ __forceinline__ void mma16816(float* d, const uint32_t* a, const uint32_t* b) {
    asm volatile(
        "mma.sync.aligned.m16n8k16.row.col.f32.bf16.bf16.f32 "
        "{%0,%1,%2,%3}, {%4,%5,%6,%7}, {%8,%9}, {%0,%1,%2,%3};"
        : "+f"(d[0]), "+f"(d[1]), "+f"(d[2]), "+f"(d[3])
        : "r"(a[0]), "r"(a[1]), "r"(a[2]), "r"(a[3]), "r"(b[0]), "r"(b[1]));
}

__device__ __forceinline__ void ldm4(uint32_t* r, uint32_t saddr) {
    asm volatile(
        "ldmatrix.sync.aligned.m8n8.x4.shared.b16 {%0,%1,%2,%3}, [%4];"
        : "=r"(r[0]), "=r"(r[1]), "=r"(r[2]), "=r"(r[3]) : "r"(saddr));
}

__device__ __forceinline__ uint32_t smem_u32(const void* p) {
    uint32_t a;
    asm("{ .reg .u64 t; cvta.to.shared.u64 t, %1; cvt.u32.u64 %0, t; }"
        : "=r"(a) : "l"(p));
    return a;
}

// smem byte offsets (rows stride SPAD bf16 = 272 B)
#define OFF_XHI   0
#define OFF_XLO   34816
#define OFF_WHI   69632
#define OFF_WLO   87040
#define SMEM_MAIN 104448

// ---------------------------------------------------------------------------
// Main: one image per block, 256 threads (8 warps), 2 blocks/SM.
// Stage1: D1[m][a] = sum_c FX[m][c] * X[a][c]   (M=64, N=128, K=128)
// Stage2: D2[n][m] = sum_a FY[n][a] * W[m][a]   (M=64, N=64,  K=128)
// 3-term bf16 split; B operands via ldmatrix.x4 (2 n-tiles per instr).
// ---------------------------------------------------------------------------
__global__ __launch_bounds__(256, 2)
void fb_main(const float* __restrict__ x,
             const float* __restrict__ xh,
             float* __restrict__ out) {
    extern __shared__ unsigned char smem[];
    const uint32_t sbase = smem_u32(smem);
    const int tid  = threadIdx.x;
    const int w    = tid >> 5;
    const int lane = tid & 31;
    const int g    = lane >> 2;
    const int t    = lane & 3;
    const int mw   = w >> 1, nw = w & 1;
    const int b = blockIdx.x, which = blockIdx.y;
    const float* __restrict__ xin = (which ? xh : x) + (size_t)b * (AA * AA);

    // ldmatrix per-lane addressing: q = matrix idx group, j = row within matrix
    const int j = lane & 7;
    const int q = lane >> 3;
    const int coff = (q & 1) * 8;       // k-half column offset
    const int rowq = (q >> 1) * 8 + j;  // row offset within 16-row tile pair

    // ---- preload FX A-fragments ----
    uint32_t fah[8][4], fal[8][4];
    {
        const uint4* fh4 = (const uint4*)g_fxhi_f + (mw * 32 + lane) * 8;
        const uint4* fl4 = (const uint4*)g_fxlo_f + (mw * 32 + lane) * 8;
        #pragma unroll
        for (int k = 0; k < 8; k++) {
            uint4 vh = fh4[k];
            fah[k][0] = vh.x; fah[k][1] = vh.y; fah[k][2] = vh.z; fah[k][3] = vh.w;
            uint4 vl = fl4[k];
            fal[k][0] = vl.x; fal[k][1] = vl.y; fal[k][2] = vl.z; fal[k][3] = vl.w;
        }
    }

    // ---- X: load fp32, split hi/lo, STS into padded smem ----
    {
        const float4* x4 = (const float4*)xin;
        #pragma unroll 4
        for (int i = tid; i < AA * AA / 4; i += 256) {
            const float4 v = x4[i];
            const int a  = i >> 5;
            const int c0 = (i & 31) * 4;
            __nv_bfloat16 h0 = __float2bfloat16(v.x), h1 = __float2bfloat16(v.y);
            __nv_bfloat16 h2 = __float2bfloat16(v.z), h3 = __float2bfloat16(v.w);
            __nv_bfloat16 l0 = __float2bfloat16(v.x - __bfloat162float(h0));
            __nv_bfloat16 l1 = __float2bfloat16(v.y - __bfloat162float(h1));
            __nv_bfloat16 l2 = __float2bfloat16(v.z - __bfloat162float(h2));
            __nv_bfloat16 l3 = __float2bfloat16(v.w - __bfloat162float(h3));
            const int boff = (a * SPAD + c0) * 2;
            *(uint2*)(smem + OFF_XHI + boff) = make_uint2(pk2(h0, h1), pk2(h2, h3));
            *(uint2*)(smem + OFF_XLO + boff) = make_uint2(pk2(l0, l1), pk2(l2, l3));
        }
    }
    __syncthreads();

    // ---- stage 1: B via ldmatrix.x4, 2 n-tiles per load ----
    {
        const int abase = nw * 64;
        float acc[8][4];
        #pragma unroll
        for (int n = 0; n < 8; n++)
            #pragma unroll
            for (int jj = 0; jj < 4; jj++) acc[n][jj] = 0.f;

        // per-pair base byte offsets (k-independent part)
        uint32_t rb[4];
        #pragma unroll
        for (int p = 0; p < 4; p++)
            rb[p] = (uint32_t)(((abase + p * 16 + rowq) * SPAD + coff) * 2);

        #pragma unroll
        for (int k = 0; k < 8; k++) {
            const uint32_t kb = (uint32_t)(k * 32);  // k*16 cols * 2B
            #pragma unroll
            for (int p = 0; p < 4; p++) {
                uint32_t bh[4], bl[4];
                const uint32_t ah = sbase + OFF_XHI + rb[p] + kb;
                ldm4(bh, ah);
                ldm4(bl, ah + (OFF_XLO - OFF_XHI));
                mma16816(acc[2 * p],     fah[k], &bh[0]);
                mma16816(acc[2 * p],     fah[k], &bl[0]);
                mma16816(acc[2 * p],     fal[k], &bh[0]);
                mma16816(acc[2 * p + 1], fah[k], &bh[2]);
                mma16816(acc[2 * p + 1], fah[k], &bl[2]);
                mma16816(acc[2 * p + 1], fal[k], &bh[2]);
            }
        }

        // preload FY A-fragments into dead fah/fal (latency hides behind stores+barrier)
        {
            const uint4* fh4 = (const uint4*)g_fyhi_f + (mw * 32 + lane) * 8;
            const uint4* fl4 = (const uint4*)g_fylo_f + (mw * 32 + lane) * 8;
            #pragma unroll
            for (int k = 0; k < 8; k++) {
                uint4 vh = fh4[k];
                fah[k][0] = vh.x; fah[k][1] = vh.y; fah[k][2] = vh.z; fah[k][3] = vh.w;
                uint4 vl = fl4[k];
                fal[k][0] = vl.x; fal[k][1] = vl.y; fal[k][2] = vl.z; fal[k][3] = vl.w;
            }
        }

        // store W[m][a] hi/lo
        #pragma unroll
        for (int n = 0; n < 8; n++) {
            const int ac = abase + n * 8 + 2 * t;
            const int r0 = mw * 16 + g, r1 = r0 + 8;
            __nv_bfloat16 h0 = __float2bfloat16(acc[n][0]);
            __nv_bfloat16 h1 = __float2bfloat16(acc[n][1]);
            __nv_bfloat16 h2 = __float2bfloat16(acc[n][2]);
            __nv_bfloat16 h3 = __float2bfloat16(acc[n][3]);
            __nv_bfloat16 l0 = __float2bfloat16(acc[n][0] - __bfloat162float(h0));
            __nv_bfloat16 l1 = __float2bfloat16(acc[n][1] - __bfloat162float(h1));
            __nv_bfloat16 l2 = __float2bfloat16(acc[n][2] - __bfloat162float(h2));
            __nv_bfloat16 l3 = __float2bfloat16(acc[n][3] - __bfloat162float(h3));
            *(uint32_t*)(smem + OFF_WHI + (r0 * SPAD + ac) * 2) = pk2(h0, h1);
            *(uint32_t*)(smem + OFF_WLO + (r0 * SPAD + ac) * 2) = pk2(l0, l1);
            *(uint32_t*)(smem + OFF_WHI + (r1 * SPAD + ac) * 2) = pk2(h2, h3);
            *(uint32_t*)(smem + OFF_WLO + (r1 * SPAD + ac) * 2) = pk2(l2, l3);
        }
    }
    __syncthreads();

    // ---- stage 2: B via ldmatrix.x4, 2 m-tiles per load ----
    {
        const int mbase = nw * 32;
        float acc[4][4];
        #pragma unroll
        for (int n = 0; n < 4; n++)
            #pragma unroll
            for (int jj = 0; jj < 4; jj++) acc[n][jj] = 0.f;

        uint32_t rb[2];
        #pragma unroll
        for (int p = 0; p < 2; p++)
            rb[p] = (uint32_t)(((mbase + p * 16 + rowq) * SPAD + coff) * 2);

        #pragma unroll
        for (int k = 0; k < 8; k++) {
            const uint32_t kb = (uint32_t)(k * 32);
            #pragma unroll
            for (int p = 0; p < 2; p++) {
                uint32_t bh[4], bl[4];
                const uint32_t ah = sbase + OFF_WHI + rb[p] + kb;
                ldm4(bh, ah);
                ldm4(bl, ah + (OFF_WLO - OFF_WHI));
                mma16816(acc[2 * p],     fah[k], &bh[0]);
                mma16816(acc[2 * p],     fah[k], &bl[0]);
                mma16816(acc[2 * p],     fal[k], &bh[0]);
                mma16816(acc[2 * p + 1], fah[k], &bh[2]);
                mma16816(acc[2 * p + 1], fah[k], &bl[2]);
                mma16816(acc[2 * p + 1], fal[k], &bh[2]);
            }
        }

        float* __restrict__ o = out + (size_t)b * (2 * NN * NN)
                                    + (size_t)which * (NN * NN);
        const int n0 = mw * 16;
        #pragma unroll
        for (int mt = 0; mt < 4; mt++) {
            const int mc = mbase + mt * 8 + 2 * t;
            *(float2*)(o + (n0 + g) * NN + mc)     = make_float2(acc[mt][0], acc[mt][1]);
            *(float2*)(o + (n0 + g + 8) * NN + mc) = make_float2(acc[mt][2], acc[mt][3]);
        }
    }
}

// ---------------------------------------------------------------------------
extern "C" void kernel_launch(void* const* d_in, const int* in_sizes, int n_in,
                              void* d_out, int out_size) {
    const float* x  = (const float*)d_in[0];
    const float* xh = (const float*)d_in[1];
    const float* h  = (const float*)d_in[2];
    const float* Ww = (const float*)d_in[3];
    const float* Wb = (const float*)d_in[4];
    float* out = (float*)d_out;

    cudaFuncSetAttribute(fb_main, cudaFuncAttributeMaxDynamicSharedMemorySize, SMEM_MAIN);

    fb_setup<<<1, 256>>>(h, Ww, Wb);
    fb_main<<<dim3(NBATCH, 2), 256, SMEM_MAIN>>>(x, xh, out);
}

// round 12
// speedup vs baseline: 3.4373x; 1.1115x over previous
#include <cuda_runtime.h>
#include <cuda_fp16.h>
#include <cstdint>

#define AA 128
#define NN 64
#define HD 512
#define NBATCH 2048
#define SPAD 136   // padded row stride in fp16 (68 words == 4 mod 32 -> ldmatrix conflict-free)

// ---------------------------------------------------------------------------
// Filterbanks (fp16 hi only) in MMA A-fragment order, packed pairs.
// Index: ((tile*32 + lane)*8 + k)*4 + r   ; tile = m-tile of 16 rows (0..3)
//   row = tile*16 + g + (r&1)*8,  col = k*16 + 2t + (r>>1)*8
// g_fy has gamma folded in.
// ---------------------------------------------------------------------------
__device__ uint32_t g_fxhi_f[4096];
__device__ uint32_t g_fyhi_f[4096];

__device__ __forceinline__ uint32_t pk2h(__half a, __half b) {
    return (uint32_t)__half_as_ushort(a) | ((uint32_t)__half_as_ushort(b) << 16);
}

// ---------------------------------------------------------------------------
// Setup: params from h[0], normalization, emit fragment-ordered fp16 arrays.
// ---------------------------------------------------------------------------
__global__ void fb_setup(const float* __restrict__ h,
                         const float* __restrict__ Ww,
                         const float* __restrict__ Wb) {
    __shared__ float p[5];
    __shared__ float redx[256], redy[256];
    __shared__ float scales[2];
    const int tid = threadIdx.x, wid = tid >> 5, lane = tid & 31;

    if (wid < 5) {
        float s = 0.f;
        for (int k = lane; k < HD; k += 32) s += h[k] * Ww[wid * HD + k];
        #pragma unroll
        for (int o = 16; o; o >>= 1) s += __shfl_down_sync(0xffffffffu, s, o);
        if (lane == 0) p[wid] = s + Wb[wid];
    }
    __syncthreads();

    const float var   = expf(p[2] + 1e-8f);
    const float d     = expf(p[3]) * (float)(AA - 1) / (float)(NN - 1);
    const float gamma = expf(p[4]);
    const float gX    = (float)(AA + 1) * (p[0] + 1.f) * 0.5f;
    const float gY    = (float)(AA + 1) * (p[1] + 1.f) * 0.5f;
    const float inv2v = 0.5f / var;

    float sx = 0.f, sy = 0.f;
    for (int idx = tid; idx < NN * AA; idx += 256) {
        const int m = idx >> 7, c = idx & 127;
        const float off = ((float)m - 32.5f) * d;
        const float dx = (float)c - (gX + off);
        const float dy = (float)c - (gY + off);
        sx += expf(-dx * dx * inv2v);
        sy += expf(-dy * dy * inv2v);
    }
    redx[tid] = sx; redy[tid] = sy;
    __syncthreads();
    for (int s = 128; s; s >>= 1) {
        if (tid < s) { redx[tid] += redx[tid + s]; redy[tid] += redy[tid + s]; }
        __syncthreads();
    }
    if (tid == 0) { scales[0] = 1.f / redx[0]; scales[1] = gamma / redy[0]; }
    __syncthreads();
    const float isx = scales[0], gsy = scales[1];

    for (int i = tid; i < 4096; i += 256) {
        const int r    = i & 3;
        const int k    = (i >> 2) & 7;
        const int lne  = (i >> 5) & 31;
        const int tile = i >> 10;
        const int g    = lne >> 2, t = lne & 3;
        const int row  = tile * 16 + g + (r & 1) * 8;
        const int col  = k * 16 + 2 * t + (r >> 1) * 8;
        const float off = ((float)row - 32.5f) * d;

        float dx0 = (float)col - (gX + off), dx1 = (float)(col + 1) - (gX + off);
        float vx0 = expf(-dx0 * dx0 * inv2v) * isx;
        float vx1 = expf(-dx1 * dx1 * inv2v) * isx;
        g_fxhi_f[i] = pk2h(__float2half(vx0), __float2half(vx1));

        float dy0 = (float)col - (gY + off), dy1 = (float)(col + 1) - (gY + off);
        float vy0 = expf(-dy0 * dy0 * inv2v) * gsy;
        float vy1 = expf(-dy1 * dy1 * inv2v) * gsy;
        g_fyhi_f[i] = pk2h(__float2half(vy0), __float2half(vy1));
    }
}

// ---------------------------------------------------------------------------
// MMA + ldmatrix (base PTX)
// ---------------------------------------------------------------------------
__device__ __forceinline__ void mma16816(float* d, const uint32_t* a, const uint32_t* b) {
    asm volatile(
        "mma.sync.aligned.m16n8k16.row.col.f32.f16.f16.f32 "
        "{%0,%1,%2,%3}, {%4,%5,%6,%7}, {%8,%9}, {%0,%1,%2,%3};"
        : "+f"(d[0]), "+f"(d[1]), "+f"(d[2]), "+f"(d[3])
        : "r"(a[0]), "r"(a[1]), "r"(a[2]), "r"(a[3]), "r"(b[0]), "r"(b[1]));
}

__device__ __forceinline__ void ldm4(uint32_t* r, uint32_t saddr) {
    asm volatile(
        "ldmatrix.sync.aligned.m8n8.x4.shared.b16 {%0,%1,%2,%3}, [%4];"
        : "=r"(r[0]), "=r"(r[1]), "=r"(r[2]), "=r"(r[3]) : "r"(saddr));
}

__device__ __forceinline__ uint32_t smem_u32(const void* p) {
    uint32_t a;
    asm("{ .reg .u64 t; cvta.to.shared.u64 t, %1; cvt.u32.u64 %0, t; }"
        : "=r"(a) : "l"(p));
    return a;
}

// smem byte offsets (rows stride SPAD fp16 = 272 B)
#define OFF_XHI   0
#define OFF_XLO   34816
#define OFF_WHI   69632
#define OFF_WLO   87040
#define SMEM_MAIN 104448

// ---------------------------------------------------------------------------
// Main: one image per block, 256 threads (8 warps), 2 blocks/SM.
// Stage1: D1[m][a] = sum_c FX[m][c] * X[a][c]   (M=64, N=128, K=128)
//   warp (wm,wq): m-range wm*32 (2 tiles), a-range wq*32 (2 ldmatrix pairs)
// Stage2: D2[n][m] = sum_a FY[n][a] * W[m][a]   (M=64, N=64,  K=128)
//   warp (wm,wq): n-range wm*32 (2 tiles), m-range wq*16 (1 pair)
// 2-term split: Fhi*(Bhi + Blo), fp16; filterbank A-frags in registers.
// ---------------------------------------------------------------------------
__global__ __launch_bounds__(256, 2)
void fb_main(const float* __restrict__ x,
             const float* __restrict__ xh,
             float* __restrict__ out) {
    extern __shared__ unsigned char smem[];
    const uint32_t sbase = smem_u32(smem);
    const int tid  = threadIdx.x;
    const int w    = tid >> 5;
    const int lane = tid & 31;
    const int g    = lane >> 2;
    const int t    = lane & 3;
    const int wm   = w & 1;    // m-half (s1) / n-half (s2)
    const int wq   = w >> 1;   // 0..3: a-quarter (s1) / m-quarter (s2)
    const int b = blockIdx.x, which = blockIdx.y;
    const float* __restrict__ xin = (which ? xh : x) + (size_t)b * (AA * AA);

    // ldmatrix per-lane addressing
    const int j = lane & 7;
    const int q = lane >> 3;
    const int coff = (q & 1) * 8;
    const int rowq = (q >> 1) * 8 + j;

    // ---- preload FX A-fragments (hi only): tiles wm*2+{0,1} ----
    uint32_t fa[2][8][4];
    {
        #pragma unroll
        for (int mt = 0; mt < 2; mt++) {
            const uint4* fh4 = (const uint4*)g_fxhi_f + ((wm * 2 + mt) * 32 + lane) * 8;
            #pragma unroll
            for (int k = 0; k < 8; k++) {
                uint4 v = fh4[k];
                fa[mt][k][0] = v.x; fa[mt][k][1] = v.y;
                fa[mt][k][2] = v.z; fa[mt][k][3] = v.w;
            }
        }
    }

    // ---- X: load fp32, split hi/lo fp16, STS into padded smem ----
    {
        const float4* x4 = (const float4*)xin;
        #pragma unroll 4
        for (int i = tid; i < AA * AA / 4; i += 256) {
            const float4 v = x4[i];
            const int a  = i >> 5;
            const int c0 = (i & 31) * 4;
            __half h0 = __float2half(v.x), h1 = __float2half(v.y);
            __half h2 = __float2half(v.z), h3 = __float2half(v.w);
            __half l0 = __float2half(v.x - __half2float(h0));
            __half l1 = __float2half(v.y - __half2float(h1));
            __half l2 = __float2half(v.z - __half2float(h2));
            __half l3 = __float2half(v.w - __half2float(h3));
            const int boff = (a * SPAD + c0) * 2;
            *(uint2*)(smem + OFF_XHI + boff) = make_uint2(pk2h(h0, h1), pk2h(h2, h3));
            *(uint2*)(smem + OFF_XLO + boff) = make_uint2(pk2h(l0, l1), pk2h(l2, l3));
        }
    }
    __syncthreads();

    // ---- stage 1 ----
    {
        const int abase = wq * 32;
        float acc[2][4][4];   // [mt][nt][reg]
        #pragma unroll
        for (int mt = 0; mt < 2; mt++)
            #pragma unroll
            for (int nt = 0; nt < 4; nt++)
                #pragma unroll
                for (int jj = 0; jj < 4; jj++) acc[mt][nt][jj] = 0.f;

        uint32_t rb[2];
        #pragma unroll
        for (int p = 0; p < 2; p++)
            rb[p] = (uint32_t)(((abase + p * 16 + rowq) * SPAD + coff) * 2);

        #pragma unroll
        for (int k = 0; k < 8; k++) {
            const uint32_t kb = (uint32_t)(k * 32);
            #pragma unroll
            for (int p = 0; p < 2; p++) {
                uint32_t bh[4], bl[4];
                const uint32_t ah = sbase + OFF_XHI + rb[p] + kb;
                ldm4(bh, ah);
                ldm4(bl, ah + (OFF_XLO - OFF_XHI));
                #pragma unroll
                for (int mt = 0; mt < 2; mt++) {
                    mma16816(acc[mt][2 * p],     fa[mt][k], &bh[0]);
                    mma16816(acc[mt][2 * p],     fa[mt][k], &bl[0]);
                    mma16816(acc[mt][2 * p + 1], fa[mt][k], &bh[2]);
                    mma16816(acc[mt][2 * p + 1], fa[mt][k], &bl[2]);
                }
            }
        }

        // preload FY A-fragments into fa (dead after stage-1 MMAs);
        // latency hides behind W stores + barrier.
        #pragma unroll
        for (int mt = 0; mt < 2; mt++) {
            const uint4* fh4 = (const uint4*)g_fyhi_f + ((wm * 2 + mt) * 32 + lane) * 8;
            #pragma unroll
            for (int k = 0; k < 8; k++) {
                uint4 v = fh4[k];
                fa[mt][k][0] = v.x; fa[mt][k][1] = v.y;
                fa[mt][k][2] = v.z; fa[mt][k][3] = v.w;
            }
        }

        // store W[m][a] hi/lo fp16
        #pragma unroll
        for (int mt = 0; mt < 2; mt++) {
            const int r0 = wm * 32 + mt * 16 + g, r1 = r0 + 8;
            #pragma unroll
            for (int nt = 0; nt < 4; nt++) {
                const int ac = abase + nt * 8 + 2 * t;
                const float* A = acc[mt][nt];
                __half h0 = __float2half(A[0]);
                __half h1 = __float2half(A[1]);
                __half h2 = __float2half(A[2]);
                __half h3 = __float2half(A[3]);
                __half l0 = __float2half(A[0] - __half2float(h0));
                __half l1 = __float2half(A[1] - __half2float(h1));
                __half l2 = __float2half(A[2] - __half2float(h2));
                __half l3 = __float2half(A[3] - __half2float(h3));
                *(uint32_t*)(smem + OFF_WHI + (r0 * SPAD + ac) * 2) = pk2h(h0, h1);
                *(uint32_t*)(smem + OFF_WLO + (r0 * SPAD + ac) * 2) = pk2h(l0, l1);
                *(uint32_t*)(smem + OFF_WHI + (r1 * SPAD + ac) * 2) = pk2h(h2, h3);
                *(uint32_t*)(smem + OFF_WLO + (r1 * SPAD + ac) * 2) = pk2h(l2, l3);
            }
        }
    }
    __syncthreads();

    // ---- stage 2 ----
    {
        const int mbase = wq * 16;
        float acc2[2][2][4];   // [A n-tile][B m-tile][reg]
        #pragma unroll
        for (int nt = 0; nt < 2; nt++)
            #pragma unroll
            for (int mb = 0; mb < 2; mb++)
                #pragma unroll
                for (int jj = 0; jj < 4; jj++) acc2[nt][mb][jj] = 0.f;

        const uint32_t rb2 = (uint32_t)(((mbase + rowq) * SPAD + coff) * 2);

        #pragma unroll
        for (int k = 0; k < 8; k++) {
            uint32_t bh[4], bl[4];
            const uint32_t ah = sbase + OFF_WHI + rb2 + (uint32_t)(k * 32);
            ldm4(bh, ah);
            ldm4(bl, ah + (OFF_WLO - OFF_WHI));
            #pragma unroll
            for (int nt = 0; nt < 2; nt++) {
                mma16816(acc2[nt][0], fa[nt][k], &bh[0]);
                mma16816(acc2[nt][0], fa[nt][k], &bl[0]);
                mma16816(acc2[nt][1], fa[nt][k], &bh[2]);
                mma16816(acc2[nt][1], fa[nt][k], &bl[2]);
            }
        }

        float* __restrict__ o = out + (size_t)b * (2 * NN * NN)
                                    + (size_t)which * (NN * NN);
        #pragma unroll
        for (int nt = 0; nt < 2; nt++) {
            const int n0 = wm * 32 + nt * 16;
            #pragma unroll
            for (int mb = 0; mb < 2; mb++) {
                const int mc = mbase + mb * 8 + 2 * t;
                *(float2*)(o + (n0 + g) * NN + mc) =
                    make_float2(acc2[nt][mb][0], acc2[nt][mb][1]);
                *(float2*)(o + (n0 + g + 8) * NN + mc) =
                    make_float2(acc2[nt][mb][2], acc2[nt][mb][3]);
            }
        }
    }
}

// ---------------------------------------------------------------------------
extern "C" void kernel_launch(void* const* d_in, const int* in_sizes, int n_in,
                              void* d_out, int out_size) {
    const float* x  = (const float*)d_in[0];
    const float* xh = (const float*)d_in[1];
    const float* h  = (const float*)d_in[2];
    const float* Ww = (const float*)d_in[3];
    const float* Wb = (const float*)d_in[4];
    float* out = (float*)d_out;

    cudaFuncSetAttribute(fb_main, cudaFuncAttributeMaxDynamicSharedMemorySize, SMEM_MAIN);

    fb_setup<<<1, 256>>>(h, Ww, Wb);
    fb_main<<<dim3(NBATCH, 2), 256, SMEM_MAIN>>>(x, xh, out);
}

// round 14
// speedup vs baseline: 3.6052x; 1.0488x over previous
#include <cuda_runtime.h>
#include <cuda_fp16.h>
#include <cstdint>

#define AA 128
#define NN 64
#define HD 512
#define NBATCH 2048
#define SPAD 136   // padded row stride in fp16 (68 words == 4 mod 32 -> ldmatrix conflict-free)

// ---------------------------------------------------------------------------
// Filterbanks (fp16) in MMA A-fragment order, packed pairs.
// Index: ((tile*32 + lane)*8 + k)*4 + r   ; tile = m-tile of 16 rows (0..3)
//   row = tile*16 + g + (r&1)*8,  col = k*16 + 2t + (r>>1)*8
// g_fy has gamma folded in.
// ---------------------------------------------------------------------------
__device__ uint32_t g_fxhi_f[4096];
__device__ uint32_t g_fyhi_f[4096];

__device__ __forceinline__ uint32_t pk2h(__half a, __half b) {
    return (uint32_t)__half_as_ushort(a) | ((uint32_t)__half_as_ushort(b) << 16);
}

// ---------------------------------------------------------------------------
// Setup: params from h[0], normalization, emit fragment-ordered fp16 arrays.
// ---------------------------------------------------------------------------
__global__ void fb_setup(const float* __restrict__ h,
                         const float* __restrict__ Ww,
                         const float* __restrict__ Wb) {
    __shared__ float p[5];
    __shared__ float redx[256], redy[256];
    __shared__ float scales[2];
    const int tid = threadIdx.x, wid = tid >> 5, lane = tid & 31;

    if (wid < 5) {
        float s = 0.f;
        for (int k = lane; k < HD; k += 32) s += h[k] * Ww[wid * HD + k];
        #pragma unroll
        for (int o = 16; o; o >>= 1) s += __shfl_down_sync(0xffffffffu, s, o);
        if (lane == 0) p[wid] = s + Wb[wid];
    }
    __syncthreads();

    const float var   = expf(p[2] + 1e-8f);
    const float d     = expf(p[3]) * (float)(AA - 1) / (float)(NN - 1);
    const float gamma = expf(p[4]);
    const float gX    = (float)(AA + 1) * (p[0] + 1.f) * 0.5f;
    const float gY    = (float)(AA + 1) * (p[1] + 1.f) * 0.5f;
    const float inv2v = 0.5f / var;

    float sx = 0.f, sy = 0.f;
    for (int idx = tid; idx < NN * AA; idx += 256) {
        const int m = idx >> 7, c = idx & 127;
        const float off = ((float)m - 32.5f) * d;
        const float dx = (float)c - (gX + off);
        const float dy = (float)c - (gY + off);
        sx += expf(-dx * dx * inv2v);
        sy += expf(-dy * dy * inv2v);
    }
    redx[tid] = sx; redy[tid] = sy;
    __syncthreads();
    for (int s = 128; s; s >>= 1) {
        if (tid < s) { redx[tid] += redx[tid + s]; redy[tid] += redy[tid + s]; }
        __syncthreads();
    }
    if (tid == 0) { scales[0] = 1.f / redx[0]; scales[1] = gamma / redy[0]; }
    __syncthreads();
    const float isx = scales[0], gsy = scales[1];

    for (int i = tid; i < 4096; i += 256) {
        const int r    = i & 3;
        const int k    = (i >> 2) & 7;
        const int lne  = (i >> 5) & 31;
        const int tile = i >> 10;
        const int g    = lne >> 2, t = lne & 3;
        const int row  = tile * 16 + g + (r & 1) * 8;
        const int col  = k * 16 + 2 * t + (r >> 1) * 8;
        const float off = ((float)row - 32.5f) * d;

        float dx0 = (float)col - (gX + off), dx1 = (float)(col + 1) - (gX + off);
        float vx0 = expf(-dx0 * dx0 * inv2v) * isx;
        float vx1 = expf(-dx1 * dx1 * inv2v) * isx;
        g_fxhi_f[i] = pk2h(__float2half(vx0), __float2half(vx1));

        float dy0 = (float)col - (gY + off), dy1 = (float)(col + 1) - (gY + off);
        float vy0 = expf(-dy0 * dy0 * inv2v) * gsy;
        float vy1 = expf(-dy1 * dy1 * inv2v) * gsy;
        g_fyhi_f[i] = pk2h(__float2half(vy0), __float2half(vy1));
    }
}

// ---------------------------------------------------------------------------
// MMA + ldmatrix (base PTX)
// ---------------------------------------------------------------------------
__device__ __forceinline__ void mma16816(float* d, const uint32_t* a, const uint32_t* b) {
    asm volatile(
        "mma.sync.aligned.m16n8k16.row.col.f32.f16.f16.f32 "
        "{%0,%1,%2,%3}, {%4,%5,%6,%7}, {%8,%9}, {%0,%1,%2,%3};"
        : "+f"(d[0]), "+f"(d[1]), "+f"(d[2]), "+f"(d[3])
        : "r"(a[0]), "r"(a[1]), "r"(a[2]), "r"(a[3]), "r"(b[0]), "r"(b[1]));
}

__device__ __forceinline__ void ldm4(uint32_t* r, uint32_t saddr) {
    asm volatile(
        "ldmatrix.sync.aligned.m8n8.x4.shared.b16 {%0,%1,%2,%3}, [%4];"
        : "=r"(r[0]), "=r"(r[1]), "=r"(r[2]), "=r"(r[3]) : "r"(saddr));
}

__device__ __forceinline__ uint32_t smem_u32(const void* p) {
    uint32_t a;
    asm("{ .reg .u64 t; cvta.to.shared.u64 t, %1; cvt.u32.u64 %0, t; }"
        : "=r"(a) : "l"(p));
    return a;
}

// smem byte offsets (rows stride SPAD fp16 = 272 B)
#define OFF_XHI   0
#define OFF_WHI   34816
#define SMEM_MAIN 52224

// ---------------------------------------------------------------------------
// Main: one image per block, 256 threads (8 warps), 2 blocks/SM.
// Stage1: D1[m][a] = sum_c FX[m][c] * X[a][c]   (M=64, N=128, K=128)
//   warp (wm,wq): m-range wm*32 (2 tiles), a-range wq*32 (2 ldmatrix pairs)
// Stage2: D2[n][m] = sum_a FY[n][a] * W[m][a]   (M=64, N=64,  K=128)
//   warp (wm,wq): n-range wm*32 (2 tiles), m-range wq*16 (1 pair)
// Pure fp16 operands (no hi/lo split); filterbank A-frags in registers.
// ---------------------------------------------------------------------------
__global__ __launch_bounds__(256, 2)
void fb_main(const float* __restrict__ x,
             const float* __restrict__ xh,
             float* __restrict__ out) {
    extern __shared__ unsigned char smem[];
    const uint32_t sbase = smem_u32(smem);
    const int tid  = threadIdx.x;
    const int w    = tid >> 5;
    const int lane = tid & 31;
    const int g    = lane >> 2;
    const int t    = lane & 3;
    const int wm   = w & 1;    // m-half (s1) / n-half (s2)
    const int wq   = w >> 1;   // 0..3: a-quarter (s1) / m-quarter (s2)
    const int b = blockIdx.x, which = blockIdx.y;
    const float* __restrict__ xin = (which ? xh : x) + (size_t)b * (AA * AA);

    // ldmatrix per-lane addressing
    const int j = lane & 7;
    const int q = lane >> 3;
    const int coff = (q & 1) * 8;
    const int rowq = (q >> 1) * 8 + j;

    // ---- preload FX A-fragments: tiles wm*2+{0,1} ----
    uint32_t fa[2][8][4];
    {
        #pragma unroll
        for (int mt = 0; mt < 2; mt++) {
            const uint4* fh4 = (const uint4*)g_fxhi_f + ((wm * 2 + mt) * 32 + lane) * 8;
            #pragma unroll
            for (int k = 0; k < 8; k++) {
                uint4 v = fh4[k];
                fa[mt][k][0] = v.x; fa[mt][k][1] = v.y;
                fa[mt][k][2] = v.z; fa[mt][k][3] = v.w;
            }
        }
    }

    // ---- X: load fp32, convert fp16, STS into padded smem ----
    {
        const float4* x4 = (const float4*)xin;
        #pragma unroll 4
        for (int i = tid; i < AA * AA / 4; i += 256) {
            const float4 v = x4[i];
            const int a  = i >> 5;
            const int c0 = (i & 31) * 4;
            const int boff = (a * SPAD + c0) * 2;
            *(uint2*)(smem + OFF_XHI + boff) =
                make_uint2(pk2h(__float2half(v.x), __float2half(v.y)),
                           pk2h(__float2half(v.z), __float2half(v.w)));
        }
    }
    __syncthreads();

    // ---- stage 1 ----
    {
        const int abase = wq * 32;
        float acc[2][4][4];   // [mt][nt][reg]
        #pragma unroll
        for (int mt = 0; mt < 2; mt++)
            #pragma unroll
            for (int nt = 0; nt < 4; nt++)
                #pragma unroll
                for (int jj = 0; jj < 4; jj++) acc[mt][nt][jj] = 0.f;

        uint32_t rb[2];
        #pragma unroll
        for (int p = 0; p < 2; p++)
            rb[p] = (uint32_t)(((abase + p * 16 + rowq) * SPAD + coff) * 2);

        #pragma unroll
        for (int k = 0; k < 8; k++) {
            const uint32_t kb = (uint32_t)(k * 32);
            #pragma unroll
            for (int p = 0; p < 2; p++) {
                uint32_t bh[4];
                ldm4(bh, sbase + OFF_XHI + rb[p] + kb);
                #pragma unroll
                for (int mt = 0; mt < 2; mt++) {
                    mma16816(acc[mt][2 * p],     fa[mt][k], &bh[0]);
                    mma16816(acc[mt][2 * p + 1], fa[mt][k], &bh[2]);
                }
            }
        }

        // preload FY A-fragments into fa (dead after stage-1 MMAs);
        // latency hides behind W stores + barrier.
        #pragma unroll
        for (int mt = 0; mt < 2; mt++) {
            const uint4* fh4 = (const uint4*)g_fyhi_f + ((wm * 2 + mt) * 32 + lane) * 8;
            #pragma unroll
            for (int k = 0; k < 8; k++) {
                uint4 v = fh4[k];
                fa[mt][k][0] = v.x; fa[mt][k][1] = v.y;
                fa[mt][k][2] = v.z; fa[mt][k][3] = v.w;
            }
        }

        // store W[m][a] fp16
        #pragma unroll
        for (int mt = 0; mt < 2; mt++) {
            const int r0 = wm * 32 + mt * 16 + g, r1 = r0 + 8;
            #pragma unroll
            for (int nt = 0; nt < 4; nt++) {
                const int ac = abase + nt * 8 + 2 * t;
                const float* A = acc[mt][nt];
                *(uint32_t*)(smem + OFF_WHI + (r0 * SPAD + ac) * 2) =
                    pk2h(__float2half(A[0]), __float2half(A[1]));
                *(uint32_t*)(smem + OFF_WHI + (r1 * SPAD + ac) * 2) =
                    pk2h(__float2half(A[2]), __float2half(A[3]));
            }
        }
    }
    __syncthreads();

    // ---- stage 2 ----
    {
        const int mbase = wq * 16;
        float acc2[2][2][4];   // [A n-tile][B m-tile][reg]
        #pragma unroll
        for (int nt = 0; nt < 2; nt++)
            #pragma unroll
            for (int mb = 0; mb < 2; mb++)
                #pragma unroll
                for (int jj = 0; jj < 4; jj++) acc2[nt][mb][jj] = 0.f;

        const uint32_t rb2 = (uint32_t)(((mbase + rowq) * SPAD + coff) * 2);

        #pragma unroll
        for (int k = 0; k < 8; k++) {
            uint32_t bh[4];
            ldm4(bh, sbase + OFF_WHI + rb2 + (uint32_t)(k * 32));
            #pragma unroll
            for (int nt = 0; nt < 2; nt++) {
                mma16816(acc2[nt][0], fa[nt][k], &bh[0]);
                mma16816(acc2[nt][1], fa[nt][k], &bh[2]);
            }
        }

        float* __restrict__ o = out + (size_t)b * (2 * NN * NN)
                                    + (size_t)which * (NN * NN);
        #pragma unroll
        for (int nt = 0; nt < 2; nt++) {
            const int n0 = wm * 32 + nt * 16;
            #pragma unroll
            for (int mb = 0; mb < 2; mb++) {
                const int mc = mbase + mb * 8 + 2 * t;
                *(float2*)(o + (n0 + g) * NN + mc) =
                    make_float2(acc2[nt][mb][0], acc2[nt][mb][1]);
                *(float2*)(o + (n0 + g + 8) * NN + mc) =
                    make_float2(acc2[nt][mb][2], acc2[nt][mb][3]);
            }
        }
    }
}

// ---------------------------------------------------------------------------
extern "C" void kernel_launch(void* const* d_in, const int* in_sizes, int n_in,
                              void* d_out, int out_size) {
    const float* x  = (const float*)d_in[0];
    const float* xh = (const float*)d_in[1];
    const float* h  = (const float*)d_in[2];
    const float* Ww = (const float*)d_in[3];
    const float* Wb = (const float*)d_in[4];
    float* out = (float*)d_out;

    cudaFuncSetAttribute(fb_main, cudaFuncAttributeMaxDynamicSharedMemorySize, SMEM_MAIN);

    fb_setup<<<1, 256>>>(h, Ww, Wb);
    fb_main<<<dim3(NBATCH, 2), 256, SMEM_MAIN>>>(x, xh, out);
}

// round 15
// speedup vs baseline: 5.3066x; 1.4719x over previous
#include <cuda_runtime.h>
#include <cuda_fp16.h>
#include <cstdint>

#define AA 128
#define NN 64
#define HD 512
#define NBATCH 2048
#define SPAD 136   // padded row stride in fp16 (68 words == 4 mod 32 -> ldmatrix conflict-free)

// ---------------------------------------------------------------------------
// Filterbanks (fp16) in MMA A-fragment order, packed pairs, LANE-MAJOR:
//   uint32 index: ((tile*8 + k)*32 + lane)*4 + r
//   row = tile*16 + g + (r&1)*8,  col = k*16 + 2t + (r>>1)*8   (g=lane>>2,t=lane&3)
// Consecutive lanes read consecutive uint4s -> coalesced LDG.128.
// g_fy has gamma folded in.
// ---------------------------------------------------------------------------
__device__ uint32_t g_fxhi_f[4096];
__device__ uint32_t g_fyhi_f[4096];

__device__ __forceinline__ uint32_t pk2h(__half a, __half b) {
    return (uint32_t)__half_as_ushort(a) | ((uint32_t)__half_as_ushort(b) << 16);
}

// ---------------------------------------------------------------------------
// Setup: params from h[0], normalization, emit fragment-ordered fp16 arrays.
// ---------------------------------------------------------------------------
__global__ void fb_setup(const float* __restrict__ h,
                         const float* __restrict__ Ww,
                         const float* __restrict__ Wb) {
    __shared__ float p[5];
    __shared__ float redx[256], redy[256];
    __shared__ float scales[2];
    const int tid = threadIdx.x, wid = tid >> 5, lane = tid & 31;

    if (wid < 5) {
        float s = 0.f;
        for (int k = lane; k < HD; k += 32) s += h[k] * Ww[wid * HD + k];
        #pragma unroll
        for (int o = 16; o; o >>= 1) s += __shfl_down_sync(0xffffffffu, s, o);
        if (lane == 0) p[wid] = s + Wb[wid];
    }
    __syncthreads();

    const float var   = expf(p[2] + 1e-8f);
    const float d     = expf(p[3]) * (float)(AA - 1) / (float)(NN - 1);
    const float gamma = expf(p[4]);
    const float gX    = (float)(AA + 1) * (p[0] + 1.f) * 0.5f;
    const float gY    = (float)(AA + 1) * (p[1] + 1.f) * 0.5f;
    const float inv2v = 0.5f / var;

    float sx = 0.f, sy = 0.f;
    for (int idx = tid; idx < NN * AA; idx += 256) {
        const int m = idx >> 7, c = idx & 127;
        const float off = ((float)m - 32.5f) * d;
        const float dx = (float)c - (gX + off);
        const float dy = (float)c - (gY + off);
        sx += expf(-dx * dx * inv2v);
        sy += expf(-dy * dy * inv2v);
    }
    redx[tid] = sx; redy[tid] = sy;
    __syncthreads();
    for (int s = 128; s; s >>= 1) {
        if (tid < s) { redx[tid] += redx[tid + s]; redy[tid] += redy[tid + s]; }
        __syncthreads();
    }
    if (tid == 0) { scales[0] = 1.f / redx[0]; scales[1] = gamma / redy[0]; }
    __syncthreads();
    const float isx = scales[0], gsy = scales[1];

    for (int i = tid; i < 4096; i += 256) {
        const int r    = i & 3;
        const int lane2= (i >> 2) & 31;
        const int k    = (i >> 7) & 7;
        const int tile = i >> 10;
        const int g    = lane2 >> 2, t = lane2 & 3;
        const int row  = tile * 16 + g + (r & 1) * 8;
        const int col  = k * 16 + 2 * t + (r >> 1) * 8;
        const float off = ((float)row - 32.5f) * d;

        float dx0 = (float)col - (gX + off), dx1 = (float)(col + 1) - (gX + off);
        float vx0 = expf(-dx0 * dx0 * inv2v) * isx;
        float vx1 = expf(-dx1 * dx1 * inv2v) * isx;
        g_fxhi_f[i] = pk2h(__float2half(vx0), __float2half(vx1));

        float dy0 = (float)col - (gY + off), dy1 = (float)(col + 1) - (gY + off);
        float vy0 = expf(-dy0 * dy0 * inv2v) * gsy;
        float vy1 = expf(-dy1 * dy1 * inv2v) * gsy;
        g_fyhi_f[i] = pk2h(__float2half(vy0), __float2half(vy1));
    }
}

// ---------------------------------------------------------------------------
// MMA + ldmatrix (base PTX)
// ---------------------------------------------------------------------------
__device__ __forceinline__ void mma16816(float* d, const uint32_t* a, const uint32_t* b) {
    asm volatile(
        "mma.sync.aligned.m16n8k16.row.col.f32.f16.f16.f32 "
        "{%0,%1,%2,%3}, {%4,%5,%6,%7}, {%8,%9}, {%0,%1,%2,%3};"
        : "+f"(d[0]), "+f"(d[1]), "+f"(d[2]), "+f"(d[3])
        : "r"(a[0]), "r"(a[1]), "r"(a[2]), "r"(a[3]), "r"(b[0]), "r"(b[1]));
}

__device__ __forceinline__ void ldm4(uint32_t* r, uint32_t saddr) {
    asm volatile(
        "ldmatrix.sync.aligned.m8n8.x4.shared.b16 {%0,%1,%2,%3}, [%4];"
        : "=r"(r[0]), "=r"(r[1]), "=r"(r[2]), "=r"(r[3]) : "r"(saddr));
}

__device__ __forceinline__ uint32_t smem_u32(const void* p) {
    uint32_t a;
    asm("{ .reg .u64 t; cvta.to.shared.u64 t, %1; cvt.u32.u64 %0, t; }"
        : "=r"(a) : "l"(p));
    return a;
}

// smem byte offsets (rows stride SPAD fp16 = 272 B)
#define OFF_XHI   0
#define OFF_WHI   34816
#define SMEM_MAIN 52224

// ---------------------------------------------------------------------------
// Main: one image per block, 256 threads (8 warps), 2 blocks/SM.
// Stage1: D1[m][a] = sum_c FX[m][c] * X[a][c]   (M=64, N=128, K=128)
//   warp (wm,wq): m-range wm*32 (2 tiles), a-range wq*32 (2 ldmatrix pairs)
// Stage2: D2[n][m] = sum_a FY[n][a] * W[m][a]   (M=64, N=64,  K=128)
//   warp (wm,wq): n-range wm*32 (2 tiles), m-range wq*16 (1 pair)
// Pure fp16 operands; filterbank A-frags preloaded via coalesced LDG.128.
// ---------------------------------------------------------------------------
__global__ __launch_bounds__(256, 2)
void fb_main(const float* __restrict__ x,
             const float* __restrict__ xh,
             float* __restrict__ out) {
    extern __shared__ unsigned char smem[];
    const uint32_t sbase = smem_u32(smem);
    const int tid  = threadIdx.x;
    const int w    = tid >> 5;
    const int lane = tid & 31;
    const int g    = lane >> 2;
    const int t    = lane & 3;
    const int wm   = w & 1;    // m-half (s1) / n-half (s2)
    const int wq   = w >> 1;   // 0..3: a-quarter (s1) / m-quarter (s2)
    const int b = blockIdx.x, which = blockIdx.y;
    const float* __restrict__ xin = (which ? xh : x) + (size_t)b * (AA * AA);

    // ldmatrix per-lane addressing
    const int j = lane & 7;
    const int q = lane >> 3;
    const int coff = (q & 1) * 8;
    const int rowq = (q >> 1) * 8 + j;

    // ---- preload FX A-fragments: tiles wm*2+{0,1}, lane-major coalesced ----
    uint32_t fa[2][8][4];
    {
        #pragma unroll
        for (int mt = 0; mt < 2; mt++) {
            const uint4* fh4 = (const uint4*)g_fxhi_f + (wm * 2 + mt) * 256 + lane;
            #pragma unroll
            for (int k = 0; k < 8; k++) {
                uint4 v = fh4[k * 32];
                fa[mt][k][0] = v.x; fa[mt][k][1] = v.y;
                fa[mt][k][2] = v.z; fa[mt][k][3] = v.w;
            }
        }
    }

    // ---- X: load fp32, convert fp16, STS into padded smem ----
    {
        const float4* x4 = (const float4*)xin;
        #pragma unroll 4
        for (int i = tid; i < AA * AA / 4; i += 256) {
            const float4 v = x4[i];
            const int a  = i >> 5;
            const int c0 = (i & 31) * 4;
            const int boff = (a * SPAD + c0) * 2;
            *(uint2*)(smem + OFF_XHI + boff) =
                make_uint2(pk2h(__float2half(v.x), __float2half(v.y)),
                           pk2h(__float2half(v.z), __float2half(v.w)));
        }
    }
    __syncthreads();

    // ---- stage 1 ----
    {
        const int abase = wq * 32;
        float acc[2][4][4];   // [mt][nt][reg]
        #pragma unroll
        for (int mt = 0; mt < 2; mt++)
            #pragma unroll
            for (int nt = 0; nt < 4; nt++)
                #pragma unroll
                for (int jj = 0; jj < 4; jj++) acc[mt][nt][jj] = 0.f;

        uint32_t rb[2];
        #pragma unroll
        for (int p = 0; p < 2; p++)
            rb[p] = (uint32_t)(((abase + p * 16 + rowq) * SPAD + coff) * 2);

        #pragma unroll
        for (int k = 0; k < 8; k++) {
            const uint32_t kb = (uint32_t)(k * 32);
            #pragma unroll
            for (int p = 0; p < 2; p++) {
                uint32_t bh[4];
                ldm4(bh, sbase + OFF_XHI + rb[p] + kb);
                #pragma unroll
                for (int mt = 0; mt < 2; mt++) {
                    mma16816(acc[mt][2 * p],     fa[mt][k], &bh[0]);
                    mma16816(acc[mt][2 * p + 1], fa[mt][k], &bh[2]);
                }
            }
        }

        // preload FY A-fragments into fa (dead after stage-1 MMAs);
        // latency hides behind W stores + barrier. Lane-major coalesced.
        #pragma unroll
        for (int mt = 0; mt < 2; mt++) {
            const uint4* fh4 = (const uint4*)g_fyhi_f + (wm * 2 + mt) * 256 + lane;
            #pragma unroll
            for (int k = 0; k < 8; k++) {
                uint4 v = fh4[k * 32];
                fa[mt][k][0] = v.x; fa[mt][k][1] = v.y;
                fa[mt][k][2] = v.z; fa[mt][k][3] = v.w;
            }
        }

        // store W[m][a] fp16
        #pragma unroll
        for (int mt = 0; mt < 2; mt++) {
            const int r0 = wm * 32 + mt * 16 + g, r1 = r0 + 8;
            #pragma unroll
            for (int nt = 0; nt < 4; nt++) {
                const int ac = abase + nt * 8 + 2 * t;
                const float* A = acc[mt][nt];
                *(uint32_t*)(smem + OFF_WHI + (r0 * SPAD + ac) * 2) =
                    pk2h(__float2half(A[0]), __float2half(A[1]));
                *(uint32_t*)(smem + OFF_WHI + (r1 * SPAD + ac) * 2) =
                    pk2h(__float2half(A[2]), __float2half(A[3]));
            }
        }
    }
    __syncthreads();

    // ---- stage 2 ----
    {
        const int mbase = wq * 16;
        float acc2[2][2][4];   // [A n-tile][B m-tile][reg]
        #pragma unroll
        for (int nt = 0; nt < 2; nt++)
            #pragma unroll
            for (int mb = 0; mb < 2; mb++)
                #pragma unroll
                for (int jj = 0; jj < 4; jj++) acc2[nt][mb][jj] = 0.f;

        const uint32_t rb2 = (uint32_t)(((mbase + rowq) * SPAD + coff) * 2);

        #pragma unroll
        for (int k = 0; k < 8; k++) {
            uint32_t bh[4];
            ldm4(bh, sbase + OFF_WHI + rb2 + (uint32_t)(k * 32));
            #pragma unroll
            for (int nt = 0; nt < 2; nt++) {
                mma16816(acc2[nt][0], fa[nt][k], &bh[0]);
                mma16816(acc2[nt][1], fa[nt][k], &bh[2]);
            }
        }

        float* __restrict__ o = out + (size_t)b * (2 * NN * NN)
                                    + (size_t)which * (NN * NN);
        #pragma unroll
        for (int nt = 0; nt < 2; nt++) {
            const int n0 = wm * 32 + nt * 16;
            #pragma unroll
            for (int mb = 0; mb < 2; mb++) {
                const int mc = mbase + mb * 8 + 2 * t;
                *(float2*)(o + (n0 + g) * NN + mc) =
                    make_float2(acc2[nt][mb][0], acc2[nt][mb][1]);
                *(float2*)(o + (n0 + g + 8) * NN + mc) =
                    make_float2(acc2[nt][mb][2], acc2[nt][mb][3]);
            }
        }
    }
}

// ---------------------------------------------------------------------------
extern "C" void kernel_launch(void* const* d_in, const int* in_sizes, int n_in,
                              void* d_out, int out_size) {
    const float* x  = (const float*)d_in[0];
    const float* xh = (const float*)d_in[1];
    const float* h  = (const float*)d_in[2];
    const float* Ww = (const float*)d_in[3];
    const float* Wb = (const float*)d_in[4];
    float* out = (float*)d_out;

    cudaFuncSetAttribute(fb_main, cudaFuncAttributeMaxDynamicSharedMemorySize, SMEM_MAIN);

    fb_setup<<<1, 256>>>(h, Ww, Wb);
    fb_main<<<dim3(NBATCH, 2), 256, SMEM_MAIN>>>(x, xh, out);
}

// round 17
// speedup vs baseline: 7.6356x; 1.4389x over previous
#include <cuda_runtime.h>
#include <cuda_fp16.h>
#include <cstdint>

#define AA 128
#define NN 64
#define HD 512
#define NBATCH 2048
#define SPAD 136   // padded row stride in fp16 (68 words == 4 mod 32 -> ldmatrix conflict-free)

// ---------------------------------------------------------------------------
// Filterbanks (fp16) in MMA A-fragment order, packed pairs, LANE-MAJOR:
//   uint32 index: ((tile*8 + k)*32 + lane)*4 + r
//   row = tile*16 + g + (r&1)*8,  col = k*16 + 2t + (r>>1)*8
// g_fy has gamma folded in.
// ---------------------------------------------------------------------------
__device__ uint32_t g_fxhi_f[4096];
__device__ uint32_t g_fyhi_f[4096];

__device__ __forceinline__ uint32_t pk2h(__half a, __half b) {
    return (uint32_t)__half_as_ushort(a) | ((uint32_t)__half_as_ushort(b) << 16);
}

// ---------------------------------------------------------------------------
// Setup kernel (unchanged from R15)
// ---------------------------------------------------------------------------
__global__ void fb_setup(const float* __restrict__ h,
                         const float* __restrict__ Ww,
                         const float* __restrict__ Wb) {
    __shared__ float p[5];
    __shared__ float redx[256], redy[256];
    __shared__ float scales[2];
    const int tid = threadIdx.x, wid = tid >> 5, lane = tid & 31;

    if (wid < 5) {
        float s = 0.f;
        for (int k = lane; k < HD; k += 32) s += h[k] * Ww[wid * HD + k];
        #pragma unroll
        for (int o = 16; o; o >>= 1) s += __shfl_down_sync(0xffffffffu, s, o);
        if (lane == 0) p[wid] = s + Wb[wid];
    }
    __syncthreads();

    const float var   = expf(p[2] + 1e-8f);
    const float d     = expf(p[3]) * (float)(AA - 1) / (float)(NN - 1);
    const float gamma = expf(p[4]);
    const float gX    = (float)(AA + 1) * (p[0] + 1.f) * 0.5f;
    const float gY    = (float)(AA + 1) * (p[1] + 1.f) * 0.5f;
    const float inv2v = 0.5f / var;

    float sx = 0.f, sy = 0.f;
    for (int idx = tid; idx < NN * AA; idx += 256) {
        const int m = idx >> 7, c = idx & 127;
        const float off = ((float)m - 32.5f) * d;
        const float dx = (float)c - (gX + off);
        const float dy = (float)c - (gY + off);
        sx += expf(-dx * dx * inv2v);
        sy += expf(-dy * dy * inv2v);
    }
    redx[tid] = sx; redy[tid] = sy;
    __syncthreads();
    for (int s = 128; s; s >>= 1) {
        if (tid < s) { redx[tid] += redx[tid + s]; redy[tid] += redy[tid + s]; }
        __syncthreads();
    }
    if (tid == 0) { scales[0] = 1.f / redx[0]; scales[1] = gamma / redy[0]; }
    __syncthreads();
    const float isx = scales[0], gsy = scales[1];

    for (int i = tid; i < 4096; i += 256) {
        const int r    = i & 3;
        const int lane2= (i >> 2) & 31;
        const int k    = (i >> 7) & 7;
        const int tile = i >> 10;
        const int g    = lane2 >> 2, t = lane2 & 3;
        const int row  = tile * 16 + g + (r & 1) * 8;
        const int col  = k * 16 + 2 * t + (r >> 1) * 8;
        const float off = ((float)row - 32.5f) * d;

        float dx0 = (float)col - (gX + off), dx1 = (float)(col + 1) - (gX + off);
        float vx0 = expf(-dx0 * dx0 * inv2v) * isx;
        float vx1 = expf(-dx1 * dx1 * inv2v) * isx;
        g_fxhi_f[i] = pk2h(__float2half(vx0), __float2half(vx1));

        float dy0 = (float)col - (gY + off), dy1 = (float)(col + 1) - (gY + off);
        float vy0 = expf(-dy0 * dy0 * inv2v) * gsy;
        float vy1 = expf(-dy1 * dy1 * inv2v) * gsy;
        g_fyhi_f[i] = pk2h(__float2half(vy0), __float2half(vy1));
    }
}

// ---------------------------------------------------------------------------
// MMA + ldmatrix (base PTX)
// ---------------------------------------------------------------------------
__device__ __forceinline__ void mma16816(float* d, const uint32_t* a, const uint32_t* b) {
    asm volatile(
        "mma.sync.aligned.m16n8k16.row.col.f32.f16.f16.f32 "
        "{%0,%1,%2,%3}, {%4,%5,%6,%7}, {%8,%9}, {%0,%1,%2,%3};"
        : "+f"(d[0]), "+f"(d[1]), "+f"(d[2]), "+f"(d[3])
        : "r"(a[0]), "r"(a[1]), "r"(a[2]), "r"(a[3]), "r"(b[0]), "r"(b[1]));
}

__device__ __forceinline__ void ldm4(uint32_t* r, uint32_t saddr) {
    asm volatile(
        "ldmatrix.sync.aligned.m8n8.x4.shared.b16 {%0,%1,%2,%3}, [%4];"
        : "=r"(r[0]), "=r"(r[1]), "=r"(r[2]), "=r"(r[3]) : "r"(saddr));
}

__device__ __forceinline__ uint32_t smem_u32(const void* p) {
    uint32_t a;
    asm("{ .reg .u64 t; cvta.to.shared.u64 t, %1; cvt.u32.u64 %0, t; }"
        : "=r"(a) : "l"(p));
    return a;
}

__device__ __forceinline__ void prefetch_l2(const void* p) {
    asm volatile("prefetch.global.L2 [%0];" :: "l"(p));
}

// smem byte offsets (rows stride SPAD fp16 = 272 B)
#define OFF_XHI   0
#define OFF_WHI   34816
#define SMEM_MAIN 52224

// ---------------------------------------------------------------------------
// Main: one block = one batch element, BOTH images (x, x_hat), pipelined:
//   load X0 (DRAM) + prefetch X1 to L2
//   stage1(0) -> W; stage2(0) -> out; [load X1 (L2 hits) in stage-2 window]
//   stage1(1) -> W; stage2(1) -> out
// 256 threads (8 warps), 2 blocks/SM. Pure fp16 mma.sync + ldmatrix.
// ---------------------------------------------------------------------------
__global__ __launch_bounds__(256, 2)
void fb_main(const float* __restrict__ x,
             const float* __restrict__ xh,
             float* __restrict__ out) {
    extern __shared__ unsigned char smem[];
    const uint32_t sbase = smem_u32(smem);
    const int tid  = threadIdx.x;
    const int w    = tid >> 5;
    const int lane = tid & 31;
    const int g    = lane >> 2;
    const int t    = lane & 3;
    const int wm   = w & 1;    // m-half (s1) / n-half (s2)
    const int wq   = w >> 1;   // 0..3: a-quarter (s1) / m-quarter (s2)
    const int b    = blockIdx.x;

    const float* __restrict__ xin0 = x  + (size_t)b * (AA * AA);
    const float* __restrict__ xin1 = xh + (size_t)b * (AA * AA);

    // ldmatrix per-lane addressing
    const int j = lane & 7;
    const int q = lane >> 3;
    const int coff = (q & 1) * 8;
    const int rowq = (q >> 1) * 8 + j;

    // ---- preload FX A-fragments: tiles wm*2+{0,1}, lane-major coalesced ----
    uint32_t fa[2][8][4];
    #pragma unroll
    for (int mt = 0; mt < 2; mt++) {
        const uint4* fh4 = (const uint4*)g_fxhi_f + (wm * 2 + mt) * 256 + lane;
        #pragma unroll
        for (int k = 0; k < 8; k++) {
            uint4 v = fh4[k * 32];
            fa[mt][k][0] = v.x; fa[mt][k][1] = v.y;
            fa[mt][k][2] = v.z; fa[mt][k][3] = v.w;
        }
    }

    // ---- X0: load fp32 (DRAM), convert fp16, STS ----
    {
        const float4* x4 = (const float4*)xin0;
        #pragma unroll 4
        for (int i = tid; i < AA * AA / 4; i += 256) {
            const float4 v = x4[i];
            const int a  = i >> 5;
            const int c0 = (i & 31) * 4;
            const int boff = (a * SPAD + c0) * 2;
            *(uint2*)(smem + OFF_XHI + boff) =
                make_uint2(pk2h(__float2half(v.x), __float2half(v.y)),
                           pk2h(__float2half(v.z), __float2half(v.w)));
        }
    }
    // ---- prefetch X1 into L2 (migrates during stage-1/2 of image 0) ----
    {
        const float* pf = xin1 + tid * 64;
        prefetch_l2(pf);
        prefetch_l2(pf + 32);
    }
    __syncthreads();

    #pragma unroll
    for (int img = 0; img < 2; img++) {
        // ---- stage 1: D1[m][a] = sum_c FX[m][c]*X[a][c] ----
        {
            const int abase = wq * 32;
            float acc[2][4][4];
            #pragma unroll
            for (int mt = 0; mt < 2; mt++)
                #pragma unroll
                for (int nt = 0; nt < 4; nt++)
                    #pragma unroll
                    for (int jj = 0; jj < 4; jj++) acc[mt][nt][jj] = 0.f;

            uint32_t rb[2];
            #pragma unroll
            for (int p = 0; p < 2; p++)
                rb[p] = (uint32_t)(((abase + p * 16 + rowq) * SPAD + coff) * 2);

            #pragma unroll
            for (int k = 0; k < 8; k++) {
                const uint32_t kb = (uint32_t)(k * 32);
                #pragma unroll
                for (int p = 0; p < 2; p++) {
                    uint32_t bh[4];
                    ldm4(bh, sbase + OFF_XHI + rb[p] + kb);
                    #pragma unroll
                    for (int mt = 0; mt < 2; mt++) {
                        mma16816(acc[mt][2 * p],     fa[mt][k], &bh[0]);
                        mma16816(acc[mt][2 * p + 1], fa[mt][k], &bh[2]);
                    }
                }
            }

            // swap fa -> FY (dead after stage-1 MMAs); hides behind W stores
            #pragma unroll
            for (int mt = 0; mt < 2; mt++) {
                const uint4* fh4 = (const uint4*)g_fyhi_f + (wm * 2 + mt) * 256 + lane;
                #pragma unroll
                for (int k = 0; k < 8; k++) {
                    uint4 v = fh4[k * 32];
                    fa[mt][k][0] = v.x; fa[mt][k][1] = v.y;
                    fa[mt][k][2] = v.z; fa[mt][k][3] = v.w;
                }
            }

            // store W[m][a] fp16
            #pragma unroll
            for (int mt = 0; mt < 2; mt++) {
                const int r0 = wm * 32 + mt * 16 + g, r1 = r0 + 8;
                #pragma unroll
                for (int nt = 0; nt < 4; nt++) {
                    const int ac = abase + nt * 8 + 2 * t;
                    const float* A = acc[mt][nt];
                    *(uint32_t*)(smem + OFF_WHI + (r0 * SPAD + ac) * 2) =
                        pk2h(__float2half(A[0]), __float2half(A[1]));
                    *(uint32_t*)(smem + OFF_WHI + (r1 * SPAD + ac) * 2) =
                        pk2h(__float2half(A[2]), __float2half(A[3]));
                }
            }
        }
        __syncthreads();

        // ---- stage 2: D2[n][m] = sum_a FY[n][a]*W[m][a]; then output ----
        {
            const int mbase = wq * 16;
            float acc2[2][2][4];
            #pragma unroll
            for (int nt = 0; nt < 2; nt++)
                #pragma unroll
                for (int mb = 0; mb < 2; mb++)
                    #pragma unroll
                    for (int jj = 0; jj < 4; jj++) acc2[nt][mb][jj] = 0.f;

            const uint32_t rb2 = (uint32_t)(((mbase + rowq) * SPAD + coff) * 2);

            #pragma unroll
            for (int k = 0; k < 8; k++) {
                uint32_t bh[4];
                ldm4(bh, sbase + OFF_WHI + rb2 + (uint32_t)(k * 32));
                #pragma unroll
                for (int nt = 0; nt < 2; nt++) {
                    mma16816(acc2[nt][0], fa[nt][k], &bh[0]);
                    mma16816(acc2[nt][1], fa[nt][k], &bh[2]);
                }
            }

            float* __restrict__ o = out + (size_t)b * (2 * NN * NN)
                                        + (size_t)img * (NN * NN);
            #pragma unroll
            for (int nt = 0; nt < 2; nt++) {
                const int n0 = wm * 32 + nt * 16;
                #pragma unroll
                for (int mb = 0; mb < 2; mb++) {
                    const int mc = mbase + mb * 8 + 2 * t;
                    *(float2*)(o + (n0 + g) * NN + mc) =
                        make_float2(acc2[nt][mb][0], acc2[nt][mb][1]);
                    *(float2*)(o + (n0 + g + 8) * NN + mc) =
                        make_float2(acc2[nt][mb][2], acc2[nt][mb][3]);
                }
            }
        }

        // ---- pipeline: load X1 (L2-resident) + restore FX frags, then sync ----
        if (img == 0) {
            const float4* x4 = (const float4*)xin1;
            #pragma unroll 4
            for (int i = tid; i < AA * AA / 4; i += 256) {
                const float4 v = x4[i];
                const int a  = i >> 5;
                const int c0 = (i & 31) * 4;
                const int boff = (a * SPAD + c0) * 2;
                *(uint2*)(smem + OFF_XHI + boff) =
                    make_uint2(pk2h(__float2half(v.x), __float2half(v.y)),
                               pk2h(__float2half(v.z), __float2half(v.w)));
            }
            #pragma unroll
            for (int mt = 0; mt < 2; mt++) {
                const uint4* fh4 = (const uint4*)g_fxhi_f + (wm * 2 + mt) * 256 + lane;
                #pragma unroll
                for (int k = 0; k < 8; k++) {
                    uint4 v = fh4[k * 32];
                    fa[mt][k][0] = v.x; fa[mt][k][1] = v.y;
                    fa[mt][k][2] = v.z; fa[mt][k][3] = v.w;
                }
            }
            __syncthreads();   // orders: W reads done, X1 ready for stage1(1)
        }
    }
}

// ---------------------------------------------------------------------------
extern "C" void kernel_launch(void* const* d_in, const int* in_sizes, int n_in,
                              void* d_out, int out_size) {
    const float* x  = (const float*)d_in[0];
    const float* xh = (const float*)d_in[1];
    const float* h  = (const float*)d_in[2];
    const float* Ww = (const float*)d_in[3];
    const float* Wb = (const float*)d_in[4];
    float* out = (float*)d_out;

    cudaFuncSetAttribute(fb_main, cudaFuncAttributeMaxDynamicSharedMemorySize, SMEM_MAIN);

    fb_setup<<<1, 256>>>(h, Ww, Wb);
    fb_main<<<NBATCH, 256, SMEM_MAIN>>>(x, xh, out);
}